// round 9
// baseline (speedup 1.0000x reference)
#include <cuda_runtime.h>
#include <cuda_bf16.h>
#include <cstdint>

// Problem constants
#define D_MODEL 1024
#define NTOK    8192          // B*L = 8*1024
#define NPAIR   128           // N_HEADS * B = 16*8
#define LSEQ    1024
#define DK      64

// ---------------------------------------------------------------------------
// Scratch (device globals — allocation-free rule)
// ---------------------------------------------------------------------------
__device__ float g_Q[NTOK * D_MODEL];
__device__ float g_K[NTOK * D_MODEL];
__device__ float g_V[NTOK * D_MODEL];

// bf16 split pairs
__device__ __nv_bfloat16 g_y0[NTOK * D_MODEL];
__device__ __nv_bfloat16 g_y1[NTOK * D_MODEL];
__device__ __nv_bfloat16 g_c0[NTOK * D_MODEL];       // AV out (split)
__device__ __nv_bfloat16 g_c1[NTOK * D_MODEL];
__device__ __nv_bfloat16 g_v0t[NTOK * D_MODEL];      // per-pair V^T split [64][1024]
__device__ __nv_bfloat16 g_v1t[NTOK * D_MODEL];
__device__ __nv_bfloat16 g_P0[(size_t)NPAIR * LSEQ * LSEQ];  // P split hi
__device__ __nv_bfloat16 g_P1[(size_t)NPAIR * LSEQ * LSEQ];  // P split lo
__device__ __nv_bfloat16 g_wv0[D_MODEL * D_MODEL];   // W^T splits
__device__ __nv_bfloat16 g_wv1[D_MODEL * D_MODEL];
__device__ __nv_bfloat16 g_wo0[D_MODEL * D_MODEL];
__device__ __nv_bfloat16 g_wo1[D_MODEL * D_MODEL];

// ---------------------------------------------------------------------------
// PTX helpers
// ---------------------------------------------------------------------------
__device__ __forceinline__ uint32_t smem_to_u32(const void* p) {
    uint32_t a;
    asm("{ .reg .u64 t; cvta.to.shared.u64 t, %1; cvt.u32.u64 %0, t; }" : "=r"(a) : "l"(p));
    return a;
}
__device__ __forceinline__ void cp_async16(uint32_t dst, const void* src) {
    asm volatile("cp.async.cg.shared.global [%0], [%1], 16;" :: "r"(dst), "l"(src));
}
#define CP_COMMIT() asm volatile("cp.async.commit_group;" ::: "memory")
#define CP_WAIT(n)  asm volatile("cp.async.wait_group %0;" :: "n"(n) : "memory")

__device__ __forceinline__ void ldmatrix_x4(uint32_t* r, uint32_t addr) {
    asm volatile("ldmatrix.sync.aligned.m8n8.x4.shared.b16 {%0,%1,%2,%3}, [%4];"
                 : "=r"(r[0]), "=r"(r[1]), "=r"(r[2]), "=r"(r[3]) : "r"(addr));
}
__device__ __forceinline__ void mma_bf16(float* d, const uint32_t* a, const uint32_t* b) {
    asm volatile(
        "mma.sync.aligned.m16n8k16.row.col.f32.bf16.bf16.f32 "
        "{%0,%1,%2,%3}, {%4,%5,%6,%7}, {%8,%9}, {%0,%1,%2,%3};"
        : "+f"(d[0]), "+f"(d[1]), "+f"(d[2]), "+f"(d[3])
        : "r"(a[0]), "r"(a[1]), "r"(a[2]), "r"(a[3]), "r"(b[0]), "r"(b[1]));
}

// Packed f32x2 FMA (sm_100+ base ISA): two independent IEEE fma.rn.f32.
__device__ __forceinline__ unsigned long long pack2(float x, float y) {
    unsigned long long r;
    asm("mov.b64 %0, {%1, %2};" : "=l"(r) : "f"(x), "f"(y));
    return r;
}
__device__ __forceinline__ void unpack2(unsigned long long r, float& x, float& y) {
    asm("mov.b64 {%0, %1}, %2;" : "=f"(x), "=f"(y) : "l"(r));
}
__device__ __forceinline__ void fma2p(unsigned long long& d, unsigned long long a,
                                      unsigned long long b) {
    asm("fma.rn.f32x2 %0, %1, %2, %3;" : "=l"(d) : "l"(a), "l"(b), "l"(d));
}

// 2-way bf16 split
__device__ __forceinline__ void bf16_split2(float f, __nv_bfloat16& h0, __nv_bfloat16& h1) {
    h0 = __float2bfloat16(f);
    h1 = __float2bfloat16(f - __bfloat162float(h0));
}

// ---------------------------------------------------------------------------
// [BIT-EXACT, FROZEN] Q/K projection: C[M,N] = A@B + bias, packed f32x2 FMAs.
// ---------------------------------------------------------------------------
__global__ __launch_bounds__(256) void sgemm_bias_kernel(
    const float* __restrict__ A, const float* __restrict__ B,
    const float* __restrict__ bias, float* __restrict__ C,
    int M, int N, int K)
{
    __shared__ float As[8][128];
    __shared__ float Bs[8][128];

    const int tid = threadIdx.x;
    const int bm = blockIdx.y * 128;
    const int bn = blockIdx.x * 128;

    const int trow = (tid / 16) * 8;
    const int tcol = (tid % 16) * 8;

    const int arow = tid / 2;
    const int acol = (tid % 2) * 4;
    const int brow = tid / 32;
    const int bcol = (tid % 32) * 4;

    unsigned long long acc2[8][4];
#pragma unroll
    for (int i = 0; i < 8; i++)
#pragma unroll
        for (int j = 0; j < 4; j++) acc2[i][j] = 0ull;

    for (int k0 = 0; k0 < K; k0 += 8) {
        float4 av = *(const float4*)&A[(size_t)(bm + arow) * K + k0 + acol];
        As[acol + 0][arow] = av.x;
        As[acol + 1][arow] = av.y;
        As[acol + 2][arow] = av.z;
        As[acol + 3][arow] = av.w;
        float4 bv = *(const float4*)&B[(size_t)(k0 + brow) * N + bn + bcol];
        *(float4*)&Bs[brow][bcol] = bv;
        __syncthreads();

#pragma unroll
        for (int k = 0; k < 8; k++) {
            float a[8], b[8];
            *(float4*)&a[0] = *(const float4*)&As[k][trow];
            *(float4*)&a[4] = *(const float4*)&As[k][trow + 4];
            *(float4*)&b[0] = *(const float4*)&Bs[k][tcol];
            *(float4*)&b[4] = *(const float4*)&Bs[k][tcol + 4];
            unsigned long long b2[4];
#pragma unroll
            for (int j = 0; j < 4; j++) b2[j] = pack2(b[2 * j], b[2 * j + 1]);
#pragma unroll
            for (int i = 0; i < 8; i++) {
                const unsigned long long a2 = pack2(a[i], a[i]);
#pragma unroll
                for (int j = 0; j < 4; j++) fma2p(acc2[i][j], a2, b2[j]);
            }
        }
        __syncthreads();
    }

    float bb[8];
    *(float4*)&bb[0] = *(const float4*)&bias[bn + tcol];
    *(float4*)&bb[4] = *(const float4*)&bias[bn + tcol + 4];

#pragma unroll
    for (int i = 0; i < 8; i++) {
        float acc[8];
#pragma unroll
        for (int j = 0; j < 4; j++) unpack2(acc2[i][j], acc[2 * j], acc[2 * j + 1]);
        const size_t r = (size_t)(bm + trow + i) * N + bn + tcol;
        float4 o0 = make_float4(acc[0] + bb[0], acc[1] + bb[1],
                                acc[2] + bb[2], acc[3] + bb[3]);
        float4 o1 = make_float4(acc[4] + bb[4], acc[5] + bb[5],
                                acc[6] + bb[6], acc[7] + bb[7]);
        *(float4*)&C[r] = o0;
        *(float4*)&C[r + 4] = o1;
    }
}

// ---------------------------------------------------------------------------
// [BIT-EXACT] Fused score + mean-mask-softmax, emits P as bf16 (hi,lo) pair.
// Block: 256 threads = 4 rowgrps x 64 u-threads; 16 rows x 1024 cols per block.
// Thread handles rows (bm + rowgrp*4 + r), cols 4u+256e (+0..3), r<4, e<4.
// Per-element fma chain: ascending k, fma.rn.f32x2 — identical bits to R1/R7.
// Reductions replicate R1 softmax's exact binary trees:
//   partial t = u + 64e over cols 4t..4t+3 (left-assoc 4-sum),
//   butterfly xor{16,8,4,2,1} == 5 lane-shfls on u (same pairing, fp add
//   commutative bitwise), warp sums W_{2e+u5}, stage-2 tree
//   ((W0+W4)+(W2+W6))+((W1+W5)+(W3+W7)) via one smem half-exchange.
// grid (LSEQ/16, NPAIR)
// ---------------------------------------------------------------------------
__global__ __launch_bounds__(256) void score_softmax_kernel(
    const float* __restrict__ Q, const float* __restrict__ Km,
    __nv_bfloat16* __restrict__ P0, __nv_bfloat16* __restrict__ P1)
{
    __shared__ float As[8][16];
    __shared__ float Bs[8][1024];
    __shared__ float sMean[16][2];
    __shared__ float sMax[16][2];
    __shared__ float sExp[16][2];

    const int z = blockIdx.y;
    const float* Qz = Q + (size_t)z * LSEQ * DK;
    const float* Kz = Km + (size_t)z * LSEQ * DK;
    const int bm = blockIdx.x * 16;
    const int tid = threadIdx.x;
    const int rowgrp = tid >> 6;     // 0..3
    const int u = tid & 63;          // 0..63
    const int u5 = u >> 5;           // half selector

    unsigned long long acc2[4][8];
#pragma unroll
    for (int r = 0; r < 4; r++)
#pragma unroll
        for (int j = 0; j < 8; j++) acc2[r][j] = 0ull;

    for (int k0 = 0; k0 < DK; k0 += 8) {
        if (tid < 32) {
            const int row = tid >> 1, kc = (tid & 1) * 4;
            float4 v = *(const float4*)&Qz[(size_t)(bm + row) * DK + k0 + kc];
            As[kc + 0][row] = v.x;
            As[kc + 1][row] = v.y;
            As[kc + 2][row] = v.z;
            As[kc + 3][row] = v.w;
        }
#pragma unroll
        for (int j = 0; j < 8; j++) {
            const int idx = tid + j * 256;
            const int l = idx >> 1, kc = (idx & 1) * 4;
            float4 v = *(const float4*)&Kz[(size_t)l * DK + k0 + kc];
            Bs[kc + 0][l] = v.x;
            Bs[kc + 1][l] = v.y;
            Bs[kc + 2][l] = v.z;
            Bs[kc + 3][l] = v.w;
        }
        __syncthreads();

#pragma unroll
        for (int k = 0; k < 8; k++) {
            float a[4];
            *(float4*)a = *(const float4*)&As[k][rowgrp * 4];
            float b[16];
#pragma unroll
            for (int e = 0; e < 4; e++)
                *(float4*)&b[4 * e] = *(const float4*)&Bs[k][4 * u + 256 * e];
            unsigned long long b2[8];
#pragma unroll
            for (int j = 0; j < 8; j++) b2[j] = pack2(b[2 * j], b[2 * j + 1]);
#pragma unroll
            for (int r = 0; r < 4; r++) {
                const unsigned long long a2 = pack2(a[r], a[r]);
#pragma unroll
                for (int j = 0; j < 8; j++) fma2p(acc2[r][j], a2, b2[j]);
            }
        }
        __syncthreads();
    }

    // Scale to score values (bit-identical to R1's stored S).
    const float scale = 0.03125f;
    float s[4][16];
#pragma unroll
    for (int r = 0; r < 4; r++) {
#pragma unroll
        for (int j = 0; j < 8; j++) unpack2(acc2[r][j], s[r][2 * j], s[r][2 * j + 1]);
#pragma unroll
        for (int c = 0; c < 16; c++) s[r][c] = s[r][c] * scale;
    }

    const int rl = rowgrp * 4;
    float mean[4], rowmax[4], inv[4];

    // ---- mean (exact R1 tree) ----
#pragma unroll
    for (int r = 0; r < 4; r++) {
        float pe[4];
#pragma unroll
        for (int e = 0; e < 4; e++)
            pe[e] = ((s[r][4 * e] + s[r][4 * e + 1]) + s[r][4 * e + 2]) + s[r][4 * e + 3];
#pragma unroll
        for (int o = 16; o > 0; o >>= 1)
#pragma unroll
            for (int e = 0; e < 4; e++)
                pe[e] += __shfl_xor_sync(0xffffffffu, pe[e], o);
        const float half = (pe[0] + pe[2]) + (pe[1] + pe[3]);
        if ((tid & 31) == 0) sMean[rl + r][u5] = half;
    }
    __syncthreads();
#pragma unroll
    for (int r = 0; r < 4; r++)
        mean[r] = (sMean[rl + r][0] + sMean[rl + r][1]) * (1.0f / 1024.0f);

    // ---- masked max (order-free: fmax is associative/commutative) ----
#pragma unroll
    for (int r = 0; r < 4; r++) {
        float m = -3.402823466e38f;
#pragma unroll
        for (int c = 0; c < 16; c++)
            if (s[r][c] > mean[r]) m = fmaxf(m, s[r][c]);
#pragma unroll
        for (int o = 16; o > 0; o >>= 1)
            m = fmaxf(m, __shfl_xor_sync(0xffffffffu, m, o));
        if ((tid & 31) == 0) sMax[rl + r][u5] = m;
    }
    __syncthreads();
#pragma unroll
    for (int r = 0; r < 4; r++)
        rowmax[r] = fmaxf(sMax[rl + r][0], sMax[rl + r][1]);

    // ---- exp (overwrite s) + sum (exact R1 tree) ----
#pragma unroll
    for (int r = 0; r < 4; r++) {
#pragma unroll
        for (int c = 0; c < 16; c++)
            s[r][c] = (s[r][c] > mean[r]) ? __expf(s[r][c] - rowmax[r]) : 0.f;
        float pe[4];
#pragma unroll
        for (int e = 0; e < 4; e++)
            pe[e] = ((s[r][4 * e] + s[r][4 * e + 1]) + s[r][4 * e + 2]) + s[r][4 * e + 3];
#pragma unroll
        for (int o = 16; o > 0; o >>= 1)
#pragma unroll
            for (int e = 0; e < 4; e++)
                pe[e] += __shfl_xor_sync(0xffffffffu, pe[e], o);
        const float half = (pe[0] + pe[2]) + (pe[1] + pe[3]);
        if ((tid & 31) == 0) sExp[rl + r][u5] = half;
    }
    __syncthreads();
#pragma unroll
    for (int r = 0; r < 4; r++)
        inv[r] = 1.0f / (sExp[rl + r][0] + sExp[rl + r][1]);

    // ---- emit P as bf16 (hi, lo) pairs ----
#pragma unroll
    for (int r = 0; r < 4; r++) {
        const size_t rowbase = ((size_t)z * LSEQ + (size_t)(bm + rl + r)) * LSEQ;
#pragma unroll
        for (int e = 0; e < 4; e++) {
            const int c0 = 4 * u + 256 * e;
            __nv_bfloat16 h0[4], h1[4];
#pragma unroll
            for (int j = 0; j < 4; j++) {
                const float p = s[r][4 * e + j] * inv[r];
                bf16_split2(p, h0[j], h1[j]);
            }
            *(__nv_bfloat162*)&P0[rowbase + c0 + 0] = __nv_bfloat162(h0[0], h0[1]);
            *(__nv_bfloat162*)&P0[rowbase + c0 + 2] = __nv_bfloat162(h0[2], h0[3]);
            *(__nv_bfloat162*)&P1[rowbase + c0 + 0] = __nv_bfloat162(h1[0], h1[1]);
            *(__nv_bfloat162*)&P1[rowbase + c0 + 2] = __nv_bfloat162(h1[2], h1[3]);
        }
    }
}

// ---------------------------------------------------------------------------
// fp32 -> bf16 (hi, lo) split. n4 = elems/4.
// ---------------------------------------------------------------------------
__global__ __launch_bounds__(256) void split2_kernel(
    const float* __restrict__ in, __nv_bfloat16* __restrict__ o0,
    __nv_bfloat16* __restrict__ o1, int n4)
{
    int i = blockIdx.x * blockDim.x + threadIdx.x;
    if (i >= n4) return;
    float4 v = ((const float4*)in)[i];
    __nv_bfloat16 a0, a1, b0, b1, c0, c1, d0, d1;
    bf16_split2(v.x, a0, a1);
    bf16_split2(v.y, b0, b1);
    bf16_split2(v.z, c0, c1);
    bf16_split2(v.w, d0, d1);
    ((__nv_bfloat162*)o0)[i * 2 + 0] = __nv_bfloat162(a0, b0);
    ((__nv_bfloat162*)o0)[i * 2 + 1] = __nv_bfloat162(c0, d0);
    ((__nv_bfloat162*)o1)[i * 2 + 0] = __nv_bfloat162(a1, b1);
    ((__nv_bfloat162*)o1)[i * 2 + 1] = __nv_bfloat162(c1, d1);
}

// ---------------------------------------------------------------------------
// W [K][N] fp32 -> split bf16 transposed [N][K]
// ---------------------------------------------------------------------------
__global__ __launch_bounds__(256) void split2_transpose_kernel(
    const float* __restrict__ W, __nv_bfloat16* __restrict__ T0,
    __nv_bfloat16* __restrict__ T1)
{
    __shared__ float t[32][33];
    const int x0 = blockIdx.x * 32;
    const int y0 = blockIdx.y * 32;
    const int tx = threadIdx.x;
#pragma unroll
    for (int i = threadIdx.y; i < 32; i += 8)
        t[i][tx] = W[(size_t)(y0 + i) * D_MODEL + x0 + tx];
    __syncthreads();
#pragma unroll
    for (int i = threadIdx.y; i < 32; i += 8) {
        float v = t[tx][i];
        __nv_bfloat16 h0, h1;
        bf16_split2(v, h0, h1);
        size_t o = (size_t)(x0 + i) * D_MODEL + y0 + tx;
        T0[o] = h0;
        T1[o] = h1;
    }
}

// ---------------------------------------------------------------------------
// Batched V^T + split: v{0,1}t[z][d][l] = split(V[z][l][d]).
// ---------------------------------------------------------------------------
__global__ __launch_bounds__(256) void vt_split_kernel(
    const float* __restrict__ V, __nv_bfloat16* __restrict__ T0,
    __nv_bfloat16* __restrict__ T1)
{
    __shared__ float t[32][33];
    const int z = blockIdx.z;
    const float* Vz = V + (size_t)z * LSEQ * DK;
    const int x0 = blockIdx.x * 32;  // d base
    const int y0 = blockIdx.y * 32;  // l base
    const int tx = threadIdx.x;
#pragma unroll
    for (int i = threadIdx.y; i < 32; i += 8)
        t[i][tx] = Vz[(size_t)(y0 + i) * DK + x0 + tx];
    __syncthreads();
#pragma unroll
    for (int i = threadIdx.y; i < 32; i += 8) {
        float v = t[tx][i];
        __nv_bfloat16 h0, h1;
        bf16_split2(v, h0, h1);
        size_t o = (size_t)z * LSEQ * DK + (size_t)(x0 + i) * LSEQ + y0 + tx;
        T0[o] = h0;
        T1[o] = h1;
    }
}

// ---------------------------------------------------------------------------
// bf16x3 GEMM: C = (A0+A1)@(B0+B1)^T + bias  (keeps a0b0, a0b1, a1b0)
// ---------------------------------------------------------------------------
#define ROWB 80
#define MATB (128 * ROWB)               // 10240
#define STAGE3B (4 * MATB)              // 40960 (a0,a1,b0,b1)
#define GEMM3_SMEM_BYTES (2 * STAGE3B)  // 81920

__global__ __launch_bounds__(256) void gemm_bf16x3(
    const __nv_bfloat16* __restrict__ A0, const __nv_bfloat16* __restrict__ A1,
    const __nv_bfloat16* __restrict__ B0, const __nv_bfloat16* __restrict__ B1,
    const float* __restrict__ bias, float* __restrict__ C, int M, int N, int K)
{
    extern __shared__ char smem[];
    const uint32_t sb = smem_to_u32(smem);
    const int tid = threadIdx.x;
    const int lane = tid & 31;
    const int wid = tid >> 5;
    const int wm = wid >> 2;
    const int wn = wid & 3;
    const int bm = blockIdx.y * 128;
    const int bn = blockIdx.x * 128;
    const int nkc = K / 32;

    float d[4][4][4];
#pragma unroll
    for (int i = 0; i < 4; i++)
#pragma unroll
        for (int j = 0; j < 4; j++)
#pragma unroll
            for (int k = 0; k < 4; k++) d[i][j][k] = 0.f;

#define G3_LOAD(stb, k0)                                                      \
    do {                                                                      \
        _Pragma("unroll")                                                     \
        for (int t = 0; t < 2; t++) {                                         \
            const int idx = tid + t * 256;                                    \
            const int row = idx >> 2, ch = idx & 3;                           \
            const uint32_t off = (uint32_t)(row * ROWB + ch * 16);            \
            const size_t ga = (size_t)(bm + row) * K + (k0) + ch * 8;         \
            const size_t gb = (size_t)(bn + row) * K + (k0) + ch * 8;         \
            cp_async16((stb) + 0 * MATB + off, A0 + ga);                      \
            cp_async16((stb) + 1 * MATB + off, A1 + ga);                      \
            cp_async16((stb) + 2 * MATB + off, B0 + gb);                      \
            cp_async16((stb) + 3 * MATB + off, B1 + gb);                      \
        }                                                                     \
    } while (0)

    G3_LOAD(sb, 0);
    CP_COMMIT();
    G3_LOAD(sb + STAGE3B, 32);
    CP_COMMIT();

    const int a_rowsel = lane & 15;
    const uint32_t a_koff = (uint32_t)((lane >> 4) << 4);
    const int b_nsel = (lane & 7) + ((lane >> 4) << 3);
    const uint32_t b_koff = (uint32_t)(((lane >> 3) & 1) << 4);

    for (int kc = 0; kc < nkc; kc++) {
        if (kc + 1 < nkc) { CP_WAIT(1); } else { CP_WAIT(0); }
        __syncthreads();

        const uint32_t st = sb + (kc & 1) * STAGE3B;

#pragma unroll
        for (int ks = 0; ks < 2; ks++) {
            const uint32_t kb = ks * 32;

            uint32_t a0[4][4], a1[4][4];
            uint32_t b0[4][2], b1[4][2];
#pragma unroll
            for (int mt = 0; mt < 4; mt++) {
                const uint32_t ra = (uint32_t)((wm * 64 + mt * 16 + a_rowsel) * ROWB) + kb + a_koff;
                ldmatrix_x4(a0[mt], st + 0 * MATB + ra);
                ldmatrix_x4(a1[mt], st + 1 * MATB + ra);
            }
#pragma unroll
            for (int ntp = 0; ntp < 2; ntp++) {
                const uint32_t rb = (uint32_t)((wn * 32 + ntp * 16 + b_nsel) * ROWB) + kb + b_koff;
                uint32_t t0[4], t1[4];
                ldmatrix_x4(t0, st + 2 * MATB + rb);
                ldmatrix_x4(t1, st + 3 * MATB + rb);
                b0[ntp * 2 + 0][0] = t0[0]; b0[ntp * 2 + 0][1] = t0[1];
                b0[ntp * 2 + 1][0] = t0[2]; b0[ntp * 2 + 1][1] = t0[3];
                b1[ntp * 2 + 0][0] = t1[0]; b1[ntp * 2 + 0][1] = t1[1];
                b1[ntp * 2 + 1][0] = t1[2]; b1[ntp * 2 + 1][1] = t1[3];
            }

#pragma unroll
            for (int mt = 0; mt < 4; mt++)
#pragma unroll
                for (int nt = 0; nt < 4; nt++) {
                    mma_bf16(d[mt][nt], a0[mt], b1[nt]);
                    mma_bf16(d[mt][nt], a1[mt], b0[nt]);
                    mma_bf16(d[mt][nt], a0[mt], b0[nt]);
                }
        }

        __syncthreads();
        if (kc + 2 < nkc) {
            const uint32_t st2 = sb + (kc & 1) * STAGE3B;
            G3_LOAD(st2, (kc + 2) * 32);
        }
        CP_COMMIT();
    }
#undef G3_LOAD

    const int lrow = lane >> 2;
    const int lcol = (lane & 3) * 2;
#pragma unroll
    for (int mt = 0; mt < 4; mt++) {
#pragma unroll
        for (int nt = 0; nt < 4; nt++) {
            const int row = bm + wm * 64 + mt * 16 + lrow;
            const int col = bn + wn * 32 + nt * 8 + lcol;
            const float bb0 = bias[col], bb1 = bias[col + 1];
            float2 v0 = make_float2(d[mt][nt][0] + bb0, d[mt][nt][1] + bb1);
            float2 v1 = make_float2(d[mt][nt][2] + bb0, d[mt][nt][3] + bb1);
            *(float2*)&C[(size_t)row * N + col] = v0;
            *(float2*)&C[(size_t)(row + 8) * N + col] = v1;
        }
    }
}

// ---------------------------------------------------------------------------
// Batched bf16x3 AV: O[z] = P[z] @ Vt[z]^T, output split to bf16 pair.
// ---------------------------------------------------------------------------
#define AV_AB (128 * ROWB)               // 10240
#define AV_BB (64 * ROWB)                // 5120
#define AV_STAGE (2 * AV_AB + 2 * AV_BB) // 30720
#define AV_SMEM_BYTES (2 * AV_STAGE)     // 61440

__global__ __launch_bounds__(256) void av_bf16x3(
    const __nv_bfloat16* __restrict__ P0, const __nv_bfloat16* __restrict__ P1,
    const __nv_bfloat16* __restrict__ V0, const __nv_bfloat16* __restrict__ V1,
    __nv_bfloat16* __restrict__ C0, __nv_bfloat16* __restrict__ C1)
{
    extern __shared__ char smem[];
    const uint32_t sb = smem_to_u32(smem);
    const int tid = threadIdx.x;
    const int lane = tid & 31;
    const int wid = tid >> 5;
    const int wm = wid >> 2;
    const int wn = wid & 3;
    const int z = blockIdx.y;
    const int bm = blockIdx.x * 128;
    const __nv_bfloat16* P0z = P0 + (size_t)z * LSEQ * LSEQ;
    const __nv_bfloat16* P1z = P1 + (size_t)z * LSEQ * LSEQ;
    const __nv_bfloat16* V0z = V0 + (size_t)z * LSEQ * DK;
    const __nv_bfloat16* V1z = V1 + (size_t)z * LSEQ * DK;

    float d[4][2][4];
#pragma unroll
    for (int i = 0; i < 4; i++)
#pragma unroll
        for (int j = 0; j < 2; j++)
#pragma unroll
            for (int k = 0; k < 4; k++) d[i][j][k] = 0.f;

#define AV_LOAD(stb, k0)                                                      \
    do {                                                                      \
        _Pragma("unroll")                                                     \
        for (int t = 0; t < 2; t++) {                                         \
            const int idx = tid + t * 256;                                    \
            const int row = idx >> 2, ch = idx & 3;                           \
            const uint32_t off = (uint32_t)(row * ROWB + ch * 16);            \
            const size_t ga = (size_t)(bm + row) * LSEQ + (k0) + ch * 8;      \
            cp_async16((stb) + 0 * AV_AB + off, P0z + ga);                    \
            cp_async16((stb) + 1 * AV_AB + off, P1z + ga);                    \
        }                                                                     \
        {                                                                     \
            const int row = tid >> 2, ch = tid & 3;                           \
            if (row < 64) {                                                   \
                const uint32_t off = (uint32_t)(row * ROWB + ch * 16);        \
                const size_t gb = (size_t)row * LSEQ + (k0) + ch * 8;         \
                cp_async16((stb) + 2 * AV_AB + off, V0z + gb);                \
                cp_async16((stb) + 2 * AV_AB + AV_BB + off, V1z + gb);        \
            }                                                                 \
        }                                                                     \
    } while (0)

    AV_LOAD(sb, 0);
    CP_COMMIT();
    AV_LOAD(sb + AV_STAGE, 32);
    CP_COMMIT();

    const int a_rowsel = lane & 15;
    const uint32_t a_koff = (uint32_t)((lane >> 4) << 4);
    const int b_nsel = (lane & 7) + ((lane >> 4) << 3);
    const uint32_t b_koff = (uint32_t)(((lane >> 3) & 1) << 4);

    const int nkc = LSEQ / 32;   // 32
    for (int kc = 0; kc < nkc; kc++) {
        if (kc + 1 < nkc) { CP_WAIT(1); } else { CP_WAIT(0); }
        __syncthreads();

        const uint32_t st = sb + (kc & 1) * AV_STAGE;

#pragma unroll
        for (int ks = 0; ks < 2; ks++) {
            const uint32_t kb = ks * 32;

            uint32_t a0[4][4], a1[4][4];
#pragma unroll
            for (int mt = 0; mt < 4; mt++) {
                const uint32_t ra = (uint32_t)((wm * 64 + mt * 16 + a_rowsel) * ROWB) + kb + a_koff;
                ldmatrix_x4(a0[mt], st + 0 * AV_AB + ra);
                ldmatrix_x4(a1[mt], st + 1 * AV_AB + ra);
            }
            uint32_t b0[2][2], b1[2][2];
            {
                const uint32_t rb = (uint32_t)((wn * 16 + b_nsel) * ROWB) + kb + b_koff;
                uint32_t t0[4], t1[4];
                ldmatrix_x4(t0, st + 2 * AV_AB + rb);
                ldmatrix_x4(t1, st + 2 * AV_AB + AV_BB + rb);
                b0[0][0] = t0[0]; b0[0][1] = t0[1];
                b0[1][0] = t0[2]; b0[1][1] = t0[3];
                b1[0][0] = t1[0]; b1[0][1] = t1[1];
                b1[1][0] = t1[2]; b1[1][1] = t1[3];
            }

#pragma unroll
            for (int mt = 0; mt < 4; mt++)
#pragma unroll
                for (int nt = 0; nt < 2; nt++) {
                    mma_bf16(d[mt][nt], a0[mt], b1[nt]);
                    mma_bf16(d[mt][nt], a1[mt], b0[nt]);
                    mma_bf16(d[mt][nt], a0[mt], b0[nt]);
                }
        }

        __syncthreads();
        if (kc + 2 < nkc) {
            const uint32_t st2 = sb + (kc & 1) * AV_STAGE;
            AV_LOAD(st2, (kc + 2) * 32);
        }
        CP_COMMIT();
    }
#undef AV_LOAD

    const int lrow = lane >> 2;
    const int lcol = (lane & 3) * 2;
#pragma unroll
    for (int mt = 0; mt < 4; mt++) {
#pragma unroll
        for (int nt = 0; nt < 2; nt++) {
            const int row = bm + wm * 64 + mt * 16 + lrow;
            const int col = wn * 16 + nt * 8 + lcol;
            const size_t o0 = (size_t)z * LSEQ * DK + (size_t)row * DK + col;
            const size_t o1 = (size_t)z * LSEQ * DK + (size_t)(row + 8) * DK + col;
            __nv_bfloat16 h0, h1, g0, g1;
            bf16_split2(d[mt][nt][0], h0, h1);
            bf16_split2(d[mt][nt][1], g0, g1);
            *(__nv_bfloat162*)&C0[o0] = __nv_bfloat162(h0, g0);
            *(__nv_bfloat162*)&C1[o0] = __nv_bfloat162(h1, g1);
            bf16_split2(d[mt][nt][2], h0, h1);
            bf16_split2(d[mt][nt][3], g0, g1);
            *(__nv_bfloat162*)&C0[o1] = __nv_bfloat162(h0, g0);
            *(__nv_bfloat162*)&C1[o1] = __nv_bfloat162(h1, g1);
        }
    }
}

// ---------------------------------------------------------------------------
extern "C" void kernel_launch(void* const* d_in, const int* in_sizes, int n_in,
                              void* d_out, int out_size)
{
    const float* x  = (const float*)d_in[0];
    const float* y  = (const float*)d_in[1];
    const float* Wq = (const float*)d_in[2];
    const float* bq = (const float*)d_in[3];
    const float* Wk = (const float*)d_in[4];
    const float* bk = (const float*)d_in[5];
    const float* Wv = (const float*)d_in[6];
    const float* bv = (const float*)d_in[7];
    const float* Wo = (const float*)d_in[8];
    const float* bo = (const float*)d_in[9];
    float* out = (float*)d_out;

    float *gQ, *gK, *gV;
    cudaGetSymbolAddress((void**)&gQ, g_Q);
    cudaGetSymbolAddress((void**)&gK, g_K);
    cudaGetSymbolAddress((void**)&gV, g_V);
    __nv_bfloat16 *y0, *y1, *c0, *c1, *v0t, *v1t, *p0, *p1;
    __nv_bfloat16 *wv0, *wv1, *wo0, *wo1;
    cudaGetSymbolAddress((void**)&y0, g_y0);
    cudaGetSymbolAddress((void**)&y1, g_y1);
    cudaGetSymbolAddress((void**)&c0, g_c0);
    cudaGetSymbolAddress((void**)&c1, g_c1);
    cudaGetSymbolAddress((void**)&v0t, g_v0t);
    cudaGetSymbolAddress((void**)&v1t, g_v1t);
    cudaGetSymbolAddress((void**)&p0, g_P0);
    cudaGetSymbolAddress((void**)&p1, g_P1);
    cudaGetSymbolAddress((void**)&wv0, g_wv0);
    cudaGetSymbolAddress((void**)&wv1, g_wv1);
    cudaGetSymbolAddress((void**)&wo0, g_wo0);
    cudaGetSymbolAddress((void**)&wo1, g_wo1);

    cudaFuncSetAttribute(gemm_bf16x3, cudaFuncAttributeMaxDynamicSharedMemorySize,
                         GEMM3_SMEM_BYTES);
    cudaFuncSetAttribute(av_bf16x3, cudaFuncAttributeMaxDynamicSharedMemorySize,
                         AV_SMEM_BYTES);

    cudaEvent_t eFork, eK, eB;
    cudaEventCreateWithFlags(&eFork, cudaEventDisableTiming);
    cudaEventCreateWithFlags(&eK, cudaEventDisableTiming);
    cudaEventCreateWithFlags(&eB, cudaEventDisableTiming);

    const cudaStream_t sMain = 0;                   // legacy default stream
    const cudaStream_t sSide = cudaStreamPerThread; // second lane, no creation

    dim3 tt(32, 8);
    dim3 tg(32, 32);
    dim3 gGemm(D_MODEL / 128, NTOK / 128);  // (8, 64)
    dim3 gSS(LSEQ / 16, NPAIR);             // (64, 128) fused score+softmax
    dim3 gVtG(DK / 32, LSEQ / 32, NPAIR);
    dim3 gAV(LSEQ / 128, NPAIR);
    const int n4 = NTOK * D_MODEL / 4;

    // Fork side lane off the main stream.
    cudaEventRecord(eFork, sMain);
    cudaStreamWaitEvent(sSide, eFork, 0);

    // Side lane: K projection (bit-exact), then the tensor-prep chain.
    sgemm_bias_kernel<<<gGemm, 256, 0, sSide>>>(y, Wk, bk, gK, NTOK, D_MODEL, D_MODEL);
    cudaEventRecord(eK, sSide);
    split2_kernel<<<(n4 + 255) / 256, 256, 0, sSide>>>(y, y0, y1, n4);
    split2_transpose_kernel<<<tg, tt, 0, sSide>>>(Wv, wv0, wv1);
    split2_transpose_kernel<<<tg, tt, 0, sSide>>>(Wo, wo0, wo1);
    gemm_bf16x3<<<gGemm, 256, GEMM3_SMEM_BYTES, sSide>>>(y0, y1, wv0, wv1, bv, gV,
                                                         NTOK, D_MODEL, D_MODEL);
    vt_split_kernel<<<gVtG, tt, 0, sSide>>>(gV, v0t, v1t);
    cudaEventRecord(eB, sSide);

    // Main lane: Q projection runs concurrently with the side lane.
    sgemm_bias_kernel<<<gGemm, 256, 0, sMain>>>(x, Wq, bq, gQ, NTOK, D_MODEL, D_MODEL);

    // Join 1: fused score+softmax needs both Q (main) and K (side).
    cudaStreamWaitEvent(sMain, eK, 0);
    score_softmax_kernel<<<gSS, 256, 0, sMain>>>(gQ, gK, p0, p1);

    // Join 2: AV needs P (main) and split V^T (side).
    cudaStreamWaitEvent(sMain, eB, 0);
    av_bf16x3<<<gAV, 256, AV_SMEM_BYTES, sMain>>>(p0, p1, v0t, v1t, c0, c1);

    gemm_bf16x3<<<gGemm, 256, GEMM3_SMEM_BYTES, sMain>>>(c0, c1, wo0, wo1, bo, out,
                                                         NTOK, D_MODEL, D_MODEL);
}

// round 10
// speedup vs baseline: 1.0176x; 1.0176x over previous
#include <cuda_runtime.h>
#include <cuda_bf16.h>
#include <cstdint>

// Problem constants
#define D_MODEL 1024
#define NTOK    8192          // B*L = 8*1024
#define NPAIR   128           // N_HEADS * B = 16*8
#define LSEQ    1024
#define DK      64

// ---------------------------------------------------------------------------
// Scratch (device globals — allocation-free rule)
// ---------------------------------------------------------------------------
__device__ float g_Q[NTOK * D_MODEL];
__device__ float g_K[NTOK * D_MODEL];
__device__ float g_V[NTOK * D_MODEL];
__device__ float g_S[(size_t)NPAIR * LSEQ * LSEQ];   // 512 MB scores

// bf16 split pairs
__device__ __nv_bfloat16 g_y0[NTOK * D_MODEL];
__device__ __nv_bfloat16 g_y1[NTOK * D_MODEL];
__device__ __nv_bfloat16 g_c0[NTOK * D_MODEL];       // AV out (split)
__device__ __nv_bfloat16 g_c1[NTOK * D_MODEL];
__device__ __nv_bfloat16 g_v0t[NTOK * D_MODEL];      // per-pair V^T split [64][1024]
__device__ __nv_bfloat16 g_v1t[NTOK * D_MODEL];
__device__ __nv_bfloat16 g_wv0[D_MODEL * D_MODEL];   // W^T splits
__device__ __nv_bfloat16 g_wv1[D_MODEL * D_MODEL];
__device__ __nv_bfloat16 g_wo0[D_MODEL * D_MODEL];
__device__ __nv_bfloat16 g_wo1[D_MODEL * D_MODEL];

// ---------------------------------------------------------------------------
// PTX helpers
// ---------------------------------------------------------------------------
__device__ __forceinline__ uint32_t smem_to_u32(const void* p) {
    uint32_t a;
    asm("{ .reg .u64 t; cvta.to.shared.u64 t, %1; cvt.u32.u64 %0, t; }" : "=r"(a) : "l"(p));
    return a;
}
__device__ __forceinline__ void cp_async16(uint32_t dst, const void* src) {
    asm volatile("cp.async.cg.shared.global [%0], [%1], 16;" :: "r"(dst), "l"(src));
}
#define CP_COMMIT() asm volatile("cp.async.commit_group;" ::: "memory")
#define CP_WAIT(n)  asm volatile("cp.async.wait_group %0;" :: "n"(n) : "memory")

__device__ __forceinline__ void ldmatrix_x4(uint32_t* r, uint32_t addr) {
    asm volatile("ldmatrix.sync.aligned.m8n8.x4.shared.b16 {%0,%1,%2,%3}, [%4];"
                 : "=r"(r[0]), "=r"(r[1]), "=r"(r[2]), "=r"(r[3]) : "r"(addr));
}
__device__ __forceinline__ void mma_bf16(float* d, const uint32_t* a, const uint32_t* b) {
    asm volatile(
        "mma.sync.aligned.m16n8k16.row.col.f32.bf16.bf16.f32 "
        "{%0,%1,%2,%3}, {%4,%5,%6,%7}, {%8,%9}, {%0,%1,%2,%3};"
        : "+f"(d[0]), "+f"(d[1]), "+f"(d[2]), "+f"(d[3])
        : "r"(a[0]), "r"(a[1]), "r"(a[2]), "r"(a[3]), "r"(b[0]), "r"(b[1]));
}

// Packed f32x2 FMA (sm_100+ base ISA): two independent IEEE fma.rn.f32.
__device__ __forceinline__ unsigned long long pack2(float x, float y) {
    unsigned long long r;
    asm("mov.b64 %0, {%1, %2};" : "=l"(r) : "f"(x), "f"(y));
    return r;
}
__device__ __forceinline__ void unpack2(unsigned long long r, float& x, float& y) {
    asm("mov.b64 {%0, %1}, %2;" : "=f"(x), "=f"(y) : "l"(r));
}
__device__ __forceinline__ void fma2p(unsigned long long& d, unsigned long long a,
                                      unsigned long long b) {
    asm("fma.rn.f32x2 %0, %1, %2, %3;" : "=l"(d) : "l"(a), "l"(b), "l"(d));
}

// 2-way bf16 split
__device__ __forceinline__ void bf16_split2(float f, __nv_bfloat16& h0, __nv_bfloat16& h1) {
    h0 = __float2bfloat16(f);
    h1 = __float2bfloat16(f - __bfloat162float(h0));
}

// ---------------------------------------------------------------------------
// [BIT-EXACT, FROZEN] Q/K projection: C[M,N] = A@B + bias, packed f32x2 FMAs.
// ---------------------------------------------------------------------------
__global__ __launch_bounds__(256) void sgemm_bias_kernel(
    const float* __restrict__ A, const float* __restrict__ B,
    const float* __restrict__ bias, float* __restrict__ C,
    int M, int N, int K)
{
    __shared__ float As[8][128];
    __shared__ float Bs[8][128];

    const int tid = threadIdx.x;
    const int bm = blockIdx.y * 128;
    const int bn = blockIdx.x * 128;

    const int trow = (tid / 16) * 8;
    const int tcol = (tid % 16) * 8;

    const int arow = tid / 2;
    const int acol = (tid % 2) * 4;
    const int brow = tid / 32;
    const int bcol = (tid % 32) * 4;

    unsigned long long acc2[8][4];
#pragma unroll
    for (int i = 0; i < 8; i++)
#pragma unroll
        for (int j = 0; j < 4; j++) acc2[i][j] = 0ull;

    for (int k0 = 0; k0 < K; k0 += 8) {
        float4 av = *(const float4*)&A[(size_t)(bm + arow) * K + k0 + acol];
        As[acol + 0][arow] = av.x;
        As[acol + 1][arow] = av.y;
        As[acol + 2][arow] = av.z;
        As[acol + 3][arow] = av.w;
        float4 bv = *(const float4*)&B[(size_t)(k0 + brow) * N + bn + bcol];
        *(float4*)&Bs[brow][bcol] = bv;
        __syncthreads();

#pragma unroll
        for (int k = 0; k < 8; k++) {
            float a[8], b[8];
            *(float4*)&a[0] = *(const float4*)&As[k][trow];
            *(float4*)&a[4] = *(const float4*)&As[k][trow + 4];
            *(float4*)&b[0] = *(const float4*)&Bs[k][tcol];
            *(float4*)&b[4] = *(const float4*)&Bs[k][tcol + 4];
            unsigned long long b2[4];
#pragma unroll
            for (int j = 0; j < 4; j++) b2[j] = pack2(b[2 * j], b[2 * j + 1]);
#pragma unroll
            for (int i = 0; i < 8; i++) {
                const unsigned long long a2 = pack2(a[i], a[i]);
#pragma unroll
                for (int j = 0; j < 4; j++) fma2p(acc2[i][j], a2, b2[j]);
            }
        }
        __syncthreads();
    }

    float bb[8];
    *(float4*)&bb[0] = *(const float4*)&bias[bn + tcol];
    *(float4*)&bb[4] = *(const float4*)&bias[bn + tcol + 4];

#pragma unroll
    for (int i = 0; i < 8; i++) {
        float acc[8];
#pragma unroll
        for (int j = 0; j < 4; j++) unpack2(acc2[i][j], acc[2 * j], acc[2 * j + 1]);
        const size_t r = (size_t)(bm + trow + i) * N + bn + tcol;
        float4 o0 = make_float4(acc[0] + bb[0], acc[1] + bb[1],
                                acc[2] + bb[2], acc[3] + bb[3]);
        float4 o1 = make_float4(acc[4] + bb[4], acc[5] + bb[5],
                                acc[6] + bb[6], acc[7] + bb[7]);
        *(float4*)&C[r] = o0;
        *(float4*)&C[r + 4] = o1;
    }
}

// ---------------------------------------------------------------------------
// [BIT-EXACT, FROZEN] Batched score: S[z] = Q[z]@K[z]^T * (1/32). Writes S.
// ---------------------------------------------------------------------------
__global__ __launch_bounds__(256) void score_kernel(
    const float* __restrict__ Q, const float* __restrict__ Km,
    float* __restrict__ S)
{
    __shared__ float As[8][128];
    __shared__ float Bs[8][128];

    const int z = blockIdx.z;
    const float* Qz = Q + (size_t)z * LSEQ * DK;
    const float* Kz = Km + (size_t)z * LSEQ * DK;
    float* Sz = S + (size_t)z * LSEQ * LSEQ;

    const int tid = threadIdx.x;
    const int bm = blockIdx.y * 128;
    const int bn = blockIdx.x * 128;
    const int trow = (tid / 16) * 8;
    const int tcol = (tid % 16) * 8;
    const int lrow = tid / 2;
    const int lcol = (tid % 2) * 4;

    unsigned long long acc2[8][4];
#pragma unroll
    for (int i = 0; i < 8; i++)
#pragma unroll
        for (int j = 0; j < 4; j++) acc2[i][j] = 0ull;

    for (int k0 = 0; k0 < DK; k0 += 8) {
        float4 av = *(const float4*)&Qz[(size_t)(bm + lrow) * DK + k0 + lcol];
        As[lcol + 0][lrow] = av.x;
        As[lcol + 1][lrow] = av.y;
        As[lcol + 2][lrow] = av.z;
        As[lcol + 3][lrow] = av.w;
        float4 bv = *(const float4*)&Kz[(size_t)(bn + lrow) * DK + k0 + lcol];
        Bs[lcol + 0][lrow] = bv.x;
        Bs[lcol + 1][lrow] = bv.y;
        Bs[lcol + 2][lrow] = bv.z;
        Bs[lcol + 3][lrow] = bv.w;
        __syncthreads();

#pragma unroll
        for (int k = 0; k < 8; k++) {
            float a[8], b[8];
            *(float4*)&a[0] = *(const float4*)&As[k][trow];
            *(float4*)&a[4] = *(const float4*)&As[k][trow + 4];
            *(float4*)&b[0] = *(const float4*)&Bs[k][tcol];
            *(float4*)&b[4] = *(const float4*)&Bs[k][tcol + 4];
            unsigned long long b2[4];
#pragma unroll
            for (int j = 0; j < 4; j++) b2[j] = pack2(b[2 * j], b[2 * j + 1]);
#pragma unroll
            for (int i = 0; i < 8; i++) {
                const unsigned long long a2 = pack2(a[i], a[i]);
#pragma unroll
                for (int j = 0; j < 4; j++) fma2p(acc2[i][j], a2, b2[j]);
            }
        }
        __syncthreads();
    }

    const float scale = 0.03125f;
#pragma unroll
    for (int i = 0; i < 8; i++) {
        float acc[8];
#pragma unroll
        for (int j = 0; j < 4; j++) unpack2(acc2[i][j], acc[2 * j], acc[2 * j + 1]);
        const size_t r = (size_t)(bm + trow + i) * LSEQ + bn + tcol;
        float4 o0 = make_float4(acc[0] * scale, acc[1] * scale,
                                acc[2] * scale, acc[3] * scale);
        float4 o1 = make_float4(acc[4] * scale, acc[5] * scale,
                                acc[6] * scale, acc[7] * scale);
        *(float4*)&Sz[r] = o0;
        *(float4*)&Sz[r + 4] = o1;
    }
}

// ---------------------------------------------------------------------------
// fp32 -> bf16 (hi, lo) split. n4 = elems/4.
// ---------------------------------------------------------------------------
__global__ __launch_bounds__(256) void split2_kernel(
    const float* __restrict__ in, __nv_bfloat16* __restrict__ o0,
    __nv_bfloat16* __restrict__ o1, int n4)
{
    int i = blockIdx.x * blockDim.x + threadIdx.x;
    if (i >= n4) return;
    float4 v = ((const float4*)in)[i];
    __nv_bfloat16 a0, a1, b0, b1, c0, c1, d0, d1;
    bf16_split2(v.x, a0, a1);
    bf16_split2(v.y, b0, b1);
    bf16_split2(v.z, c0, c1);
    bf16_split2(v.w, d0, d1);
    ((__nv_bfloat162*)o0)[i * 2 + 0] = __nv_bfloat162(a0, b0);
    ((__nv_bfloat162*)o0)[i * 2 + 1] = __nv_bfloat162(c0, d0);
    ((__nv_bfloat162*)o1)[i * 2 + 0] = __nv_bfloat162(a1, b1);
    ((__nv_bfloat162*)o1)[i * 2 + 1] = __nv_bfloat162(c1, d1);
}

// ---------------------------------------------------------------------------
// W [K][N] fp32 -> split bf16 transposed [N][K]
// ---------------------------------------------------------------------------
__global__ __launch_bounds__(256) void split2_transpose_kernel(
    const float* __restrict__ W, __nv_bfloat16* __restrict__ T0,
    __nv_bfloat16* __restrict__ T1)
{
    __shared__ float t[32][33];
    const int x0 = blockIdx.x * 32;
    const int y0 = blockIdx.y * 32;
    const int tx = threadIdx.x;
#pragma unroll
    for (int i = threadIdx.y; i < 32; i += 8)
        t[i][tx] = W[(size_t)(y0 + i) * D_MODEL + x0 + tx];
    __syncthreads();
#pragma unroll
    for (int i = threadIdx.y; i < 32; i += 8) {
        float v = t[tx][i];
        __nv_bfloat16 h0, h1;
        bf16_split2(v, h0, h1);
        size_t o = (size_t)(x0 + i) * D_MODEL + y0 + tx;
        T0[o] = h0;
        T1[o] = h1;
    }
}

// ---------------------------------------------------------------------------
// Batched V^T + split: v{0,1}t[z][d][l] = split(V[z][l][d]).
// ---------------------------------------------------------------------------
__global__ __launch_bounds__(256) void vt_split_kernel(
    const float* __restrict__ V, __nv_bfloat16* __restrict__ T0,
    __nv_bfloat16* __restrict__ T1)
{
    __shared__ float t[32][33];
    const int z = blockIdx.z;
    const float* Vz = V + (size_t)z * LSEQ * DK;
    const int x0 = blockIdx.x * 32;  // d base
    const int y0 = blockIdx.y * 32;  // l base
    const int tx = threadIdx.x;
#pragma unroll
    for (int i = threadIdx.y; i < 32; i += 8)
        t[i][tx] = Vz[(size_t)(y0 + i) * DK + x0 + tx];
    __syncthreads();
#pragma unroll
    for (int i = threadIdx.y; i < 32; i += 8) {
        float v = t[tx][i];
        __nv_bfloat16 h0, h1;
        bf16_split2(v, h0, h1);
        size_t o = (size_t)z * LSEQ * DK + (size_t)(x0 + i) * LSEQ + y0 + tx;
        T0[o] = h0;
        T1[o] = h1;
    }
}

// ---------------------------------------------------------------------------
// bf16x3 GEMM: C = (A0+A1)@(B0+B1)^T + bias  (keeps a0b0, a0b1, a1b0)
// ---------------------------------------------------------------------------
#define ROWB 80
#define MATB (128 * ROWB)               // 10240
#define STAGE3B (4 * MATB)              // 40960 (a0,a1,b0,b1)
#define GEMM3_SMEM_BYTES (2 * STAGE3B)  // 81920

__global__ __launch_bounds__(256) void gemm_bf16x3(
    const __nv_bfloat16* __restrict__ A0, const __nv_bfloat16* __restrict__ A1,
    const __nv_bfloat16* __restrict__ B0, const __nv_bfloat16* __restrict__ B1,
    const float* __restrict__ bias, float* __restrict__ C, int M, int N, int K)
{
    extern __shared__ char smem[];
    const uint32_t sb = smem_to_u32(smem);
    const int tid = threadIdx.x;
    const int lane = tid & 31;
    const int wid = tid >> 5;
    const int wm = wid >> 2;
    const int wn = wid & 3;
    const int bm = blockIdx.y * 128;
    const int bn = blockIdx.x * 128;
    const int nkc = K / 32;

    float d[4][4][4];
#pragma unroll
    for (int i = 0; i < 4; i++)
#pragma unroll
        for (int j = 0; j < 4; j++)
#pragma unroll
            for (int k = 0; k < 4; k++) d[i][j][k] = 0.f;

#define G3_LOAD(stb, k0)                                                      \
    do {                                                                      \
        _Pragma("unroll")                                                     \
        for (int t = 0; t < 2; t++) {                                         \
            const int idx = tid + t * 256;                                    \
            const int row = idx >> 2, ch = idx & 3;                           \
            const uint32_t off = (uint32_t)(row * ROWB + ch * 16);            \
            const size_t ga = (size_t)(bm + row) * K + (k0) + ch * 8;         \
            const size_t gb = (size_t)(bn + row) * K + (k0) + ch * 8;         \
            cp_async16((stb) + 0 * MATB + off, A0 + ga);                      \
            cp_async16((stb) + 1 * MATB + off, A1 + ga);                      \
            cp_async16((stb) + 2 * MATB + off, B0 + gb);                      \
            cp_async16((stb) + 3 * MATB + off, B1 + gb);                      \
        }                                                                     \
    } while (0)

    G3_LOAD(sb, 0);
    CP_COMMIT();
    G3_LOAD(sb + STAGE3B, 32);
    CP_COMMIT();

    const int a_rowsel = lane & 15;
    const uint32_t a_koff = (uint32_t)((lane >> 4) << 4);
    const int b_nsel = (lane & 7) + ((lane >> 4) << 3);
    const uint32_t b_koff = (uint32_t)(((lane >> 3) & 1) << 4);

    for (int kc = 0; kc < nkc; kc++) {
        if (kc + 1 < nkc) { CP_WAIT(1); } else { CP_WAIT(0); }
        __syncthreads();

        const uint32_t st = sb + (kc & 1) * STAGE3B;

#pragma unroll
        for (int ks = 0; ks < 2; ks++) {
            const uint32_t kb = ks * 32;

            uint32_t a0[4][4], a1[4][4];
            uint32_t b0[4][2], b1[4][2];
#pragma unroll
            for (int mt = 0; mt < 4; mt++) {
                const uint32_t ra = (uint32_t)((wm * 64 + mt * 16 + a_rowsel) * ROWB) + kb + a_koff;
                ldmatrix_x4(a0[mt], st + 0 * MATB + ra);
                ldmatrix_x4(a1[mt], st + 1 * MATB + ra);
            }
#pragma unroll
            for (int ntp = 0; ntp < 2; ntp++) {
                const uint32_t rb = (uint32_t)((wn * 32 + ntp * 16 + b_nsel) * ROWB) + kb + b_koff;
                uint32_t t0[4], t1[4];
                ldmatrix_x4(t0, st + 2 * MATB + rb);
                ldmatrix_x4(t1, st + 3 * MATB + rb);
                b0[ntp * 2 + 0][0] = t0[0]; b0[ntp * 2 + 0][1] = t0[1];
                b0[ntp * 2 + 1][0] = t0[2]; b0[ntp * 2 + 1][1] = t0[3];
                b1[ntp * 2 + 0][0] = t1[0]; b1[ntp * 2 + 0][1] = t1[1];
                b1[ntp * 2 + 1][0] = t1[2]; b1[ntp * 2 + 1][1] = t1[3];
            }

#pragma unroll
            for (int mt = 0; mt < 4; mt++)
#pragma unroll
                for (int nt = 0; nt < 4; nt++) {
                    mma_bf16(d[mt][nt], a0[mt], b1[nt]);
                    mma_bf16(d[mt][nt], a1[mt], b0[nt]);
                    mma_bf16(d[mt][nt], a0[mt], b0[nt]);
                }
        }

        __syncthreads();
        if (kc + 2 < nkc) {
            const uint32_t st2 = sb + (kc & 1) * STAGE3B;
            G3_LOAD(st2, (kc + 2) * 32);
        }
        CP_COMMIT();
    }
#undef G3_LOAD

    const int lrow = lane >> 2;
    const int lcol = (lane & 3) * 2;
#pragma unroll
    for (int mt = 0; mt < 4; mt++) {
#pragma unroll
        for (int nt = 0; nt < 4; nt++) {
            const int row = bm + wm * 64 + mt * 16 + lrow;
            const int col = bn + wn * 32 + nt * 8 + lcol;
            const float bb0 = bias[col], bb1 = bias[col + 1];
            float2 v0 = make_float2(d[mt][nt][0] + bb0, d[mt][nt][1] + bb1);
            float2 v1 = make_float2(d[mt][nt][2] + bb0, d[mt][nt][3] + bb1);
            *(float2*)&C[(size_t)row * N + col] = v0;
            *(float2*)&C[(size_t)(row + 8) * N + col] = v1;
        }
    }
}

// ---------------------------------------------------------------------------
// Fused stats + softmax + AV:  O[z] = softmax(mask(S[z])) @ Vt[z]^T.
// Phase 1: per-block exact R1-tree stats (mean/maskmax/inv) for its 128 rows
//          — reduction code lifted verbatim from the R9-validated kernel.
// Phase 2: AV mma mainloop (unchanged tiling); A-tiles produced by LDG-S +
//          mask/__expf/*inv (same ops/bits as the old softmax) + bf16 split.
// grid (LSEQ/128, NPAIR), 256 threads.
// ---------------------------------------------------------------------------
#define AVF_AB (128 * ROWB)                 // 10240 per P-split tile
#define AVF_BB (64 * ROWB)                  // 5120 per V-split tile
#define AVF_A_OFF 0                         // A bufs: 2 stages x (P0,P1)
#define AVF_V_OFF (2 * 2 * AVF_AB)          // 40960: V bufs: 2 stages x (V0,V1)
#define AVF_STATM (AVF_V_OFF + 2 * 2 * AVF_BB)   // 61440
#define AVF_STATX (AVF_STATM + 512)
#define AVF_STATI (AVF_STATX + 512)
#define AVF_RED   (AVF_STATI + 512)         // 3 x [16][2] floats = 384B
#define AVF_SMEM  (AVF_RED + 384)           // 63360

__global__ __launch_bounds__(256) void av_fused(
    const float* __restrict__ S,
    const __nv_bfloat16* __restrict__ V0, const __nv_bfloat16* __restrict__ V1,
    __nv_bfloat16* __restrict__ C0, __nv_bfloat16* __restrict__ C1)
{
    extern __shared__ char smem[];
    const uint32_t sb = smem_to_u32(smem);
    const int tid = threadIdx.x;
    const int lane = tid & 31;
    const int wid = tid >> 5;
    const int wm = wid >> 2;
    const int wn = wid & 3;
    const int z = blockIdx.y;
    const int bm = blockIdx.x * 128;
    const float* Sz = S + ((size_t)z * LSEQ + bm) * LSEQ;   // local rows 0..127
    const __nv_bfloat16* V0z = V0 + (size_t)z * LSEQ * DK;
    const __nv_bfloat16* V1z = V1 + (size_t)z * LSEQ * DK;

    float* statM = (float*)(smem + AVF_STATM);
    float* statX = (float*)(smem + AVF_STATX);
    float* statI = (float*)(smem + AVF_STATI);
    float (*rbM)[2] = (float(*)[2])(smem + AVF_RED);
    float (*rbX)[2] = rbM + 16;
    float (*rbE)[2] = rbM + 32;

    // ================= Phase 1: exact-tree row stats (R9-validated) ========
    {
        const int rowgrp = tid >> 6;     // 0..3
        const int u = tid & 63;          // 0..63
        const int u5 = u >> 5;
        const int rl = rowgrp * 4;

        for (int it = 0; it < 8; it++) {
            float s[4][16];
#pragma unroll
            for (int r = 0; r < 4; r++)
#pragma unroll
                for (int e = 0; e < 4; e++)
                    *(float4*)&s[r][4 * e] =
                        *(const float4*)&Sz[(size_t)(it * 16 + rl + r) * LSEQ + 4 * u + 256 * e];

            float mean[4], rowmax[4], inv[4];

            // ---- mean (exact R1 tree) ----
#pragma unroll
            for (int r = 0; r < 4; r++) {
                float pe[4];
#pragma unroll
                for (int e = 0; e < 4; e++)
                    pe[e] = ((s[r][4 * e] + s[r][4 * e + 1]) + s[r][4 * e + 2]) + s[r][4 * e + 3];
#pragma unroll
                for (int o = 16; o > 0; o >>= 1)
#pragma unroll
                    for (int e = 0; e < 4; e++)
                        pe[e] += __shfl_xor_sync(0xffffffffu, pe[e], o);
                const float half = (pe[0] + pe[2]) + (pe[1] + pe[3]);
                if ((tid & 31) == 0) rbM[rl + r][u5] = half;
            }
            __syncthreads();
#pragma unroll
            for (int r = 0; r < 4; r++)
                mean[r] = (rbM[rl + r][0] + rbM[rl + r][1]) * (1.0f / 1024.0f);

            // ---- masked max (order-free) ----
#pragma unroll
            for (int r = 0; r < 4; r++) {
                float m = -3.402823466e38f;
#pragma unroll
                for (int c = 0; c < 16; c++)
                    if (s[r][c] > mean[r]) m = fmaxf(m, s[r][c]);
#pragma unroll
                for (int o = 16; o > 0; o >>= 1)
                    m = fmaxf(m, __shfl_xor_sync(0xffffffffu, m, o));
                if ((tid & 31) == 0) rbX[rl + r][u5] = m;
            }
            __syncthreads();
#pragma unroll
            for (int r = 0; r < 4; r++)
                rowmax[r] = fmaxf(rbX[rl + r][0], rbX[rl + r][1]);

            // ---- exp + sum (exact R1 tree) ----
#pragma unroll
            for (int r = 0; r < 4; r++) {
#pragma unroll
                for (int c = 0; c < 16; c++)
                    s[r][c] = (s[r][c] > mean[r]) ? __expf(s[r][c] - rowmax[r]) : 0.f;
                float pe[4];
#pragma unroll
                for (int e = 0; e < 4; e++)
                    pe[e] = ((s[r][4 * e] + s[r][4 * e + 1]) + s[r][4 * e + 2]) + s[r][4 * e + 3];
#pragma unroll
                for (int o = 16; o > 0; o >>= 1)
#pragma unroll
                    for (int e = 0; e < 4; e++)
                        pe[e] += __shfl_xor_sync(0xffffffffu, pe[e], o);
                const float half = (pe[0] + pe[2]) + (pe[1] + pe[3]);
                if ((tid & 31) == 0) rbE[rl + r][u5] = half;
            }
            __syncthreads();
#pragma unroll
            for (int r = 0; r < 4; r++)
                inv[r] = 1.0f / (rbE[rl + r][0] + rbE[rl + r][1]);

            if (u == 0) {
#pragma unroll
                for (int r = 0; r < 4; r++) {
                    statM[it * 16 + rl + r] = mean[r];
                    statX[it * 16 + rl + r] = rowmax[r];
                    statI[it * 16 + rl + r] = inv[r];
                }
            }
            __syncthreads();   // rb* reuse next iteration; stats visible later
        }
    }

    // ================= Phase 2: AV mainloop with inline softmax =============
    float d[4][2][4];
#pragma unroll
    for (int i = 0; i < 4; i++)
#pragma unroll
        for (int j = 0; j < 2; j++)
#pragma unroll
            for (int k = 0; k < 4; k++) d[i][j][k] = 0.f;

    // A-staging: 4 slots per thread; slot t: idx = tid + 256t, row=idx>>3, ch=idx&7
    float4 freg[4];
#define AVF_LDGA(kc)                                                          \
    do {                                                                      \
        _Pragma("unroll")                                                     \
        for (int t = 0; t < 4; t++) {                                         \
            const int idx = tid + t * 256;                                    \
            const int row = idx >> 3, ch = idx & 7;                           \
            freg[t] = *(const float4*)&Sz[(size_t)row * LSEQ + (kc) * 32 + ch * 4]; \
        }                                                                     \
    } while (0)

#define AVF_STSA(kc)                                                          \
    do {                                                                      \
        char* ab = smem + AVF_A_OFF + ((kc) & 1) * (2 * AVF_AB);              \
        _Pragma("unroll")                                                     \
        for (int t = 0; t < 4; t++) {                                         \
            const int idx = tid + t * 256;                                    \
            const int row = idx >> 3, ch = idx & 7;                           \
            const float mu = statM[row], mx = statX[row], iv = statI[row];    \
            float sv[4] = {freg[t].x, freg[t].y, freg[t].z, freg[t].w};       \
            __nv_bfloat16 h0[4], h1[4];                                       \
            _Pragma("unroll")                                                 \
            for (int j = 0; j < 4; j++) {                                     \
                float e = (sv[j] > mu) ? __expf(sv[j] - mx) : 0.f;            \
                float p = e * iv;                                             \
                bf16_split2(p, h0[j], h1[j]);                                 \
            }                                                                 \
            __nv_bfloat162* p0p = (__nv_bfloat162*)(ab + row * ROWB + ch * 8);\
            __nv_bfloat162* p1p = (__nv_bfloat162*)(ab + AVF_AB + row * ROWB + ch * 8);\
            p0p[0] = __nv_bfloat162(h0[0], h0[1]);                            \
            p0p[1] = __nv_bfloat162(h0[2], h0[3]);                            \
            p1p[0] = __nv_bfloat162(h1[0], h1[1]);                            \
            p1p[1] = __nv_bfloat162(h1[2], h1[3]);                            \
        }                                                                     \
    } while (0)

#define AVF_LDV(kc)                                                           \
    do {                                                                      \
        const uint32_t vb = sb + AVF_V_OFF + ((kc) & 1) * (2 * AVF_BB);       \
        const int row = tid >> 2, chv = tid & 3;                              \
        if (row < 64) {                                                       \
            const uint32_t off = (uint32_t)(row * ROWB + chv * 16);           \
            const size_t gb = (size_t)row * LSEQ + (kc) * 32 + chv * 8;       \
            cp_async16(vb + off, V0z + gb);                                   \
            cp_async16(vb + AVF_BB + off, V1z + gb);                          \
        }                                                                     \
    } while (0)

    AVF_LDGA(0);
    AVF_LDV(0); CP_COMMIT();
    AVF_LDV(1); CP_COMMIT();
    AVF_STSA(0);
    AVF_LDGA(1);

    const int a_rowsel = lane & 15;
    const uint32_t a_koff = (uint32_t)((lane >> 4) << 4);
    const int b_nsel = (lane & 7) + ((lane >> 4) << 3);
    const uint32_t b_koff = (uint32_t)(((lane >> 3) & 1) << 4);

    const int nkc = LSEQ / 32;   // 32
    for (int kc = 0; kc < nkc; kc++) {
        if (kc + 1 < nkc) { CP_WAIT(1); } else { CP_WAIT(0); }
        __syncthreads();   // A(kc) STS + V(kc) visible

        const uint32_t ast = sb + AVF_A_OFF + (kc & 1) * (2 * AVF_AB);
        const uint32_t vst = sb + AVF_V_OFF + (kc & 1) * (2 * AVF_BB);

#pragma unroll
        for (int ks = 0; ks < 2; ks++) {
            const uint32_t kb = ks * 32;

            uint32_t a0[4][4], a1[4][4];
#pragma unroll
            for (int mt = 0; mt < 4; mt++) {
                const uint32_t ra = (uint32_t)((wm * 64 + mt * 16 + a_rowsel) * ROWB) + kb + a_koff;
                ldmatrix_x4(a0[mt], ast + ra);
                ldmatrix_x4(a1[mt], ast + AVF_AB + ra);
            }
            uint32_t b0[2][2], b1[2][2];
            {
                const uint32_t rb = (uint32_t)((wn * 16 + b_nsel) * ROWB) + kb + b_koff;
                uint32_t t0[4], t1[4];
                ldmatrix_x4(t0, vst + rb);
                ldmatrix_x4(t1, vst + AVF_BB + rb);
                b0[0][0] = t0[0]; b0[0][1] = t0[1];
                b0[1][0] = t0[2]; b0[1][1] = t0[3];
                b1[0][0] = t1[0]; b1[0][1] = t1[1];
                b1[1][0] = t1[2]; b1[1][1] = t1[3];
            }

#pragma unroll
            for (int mt = 0; mt < 4; mt++)
#pragma unroll
                for (int nt = 0; nt < 2; nt++) {
                    mma_bf16(d[mt][nt], a0[mt], b1[nt]);
                    mma_bf16(d[mt][nt], a1[mt], b0[nt]);
                    mma_bf16(d[mt][nt], a0[mt], b0[nt]);
                }
        }

        __syncthreads();   // all reads of buf (kc&1) done
        if (kc + 1 < nkc) AVF_STSA(kc + 1);
        if (kc + 2 < nkc) { AVF_LDGA(kc + 2); AVF_LDV(kc + 2); }
        CP_COMMIT();
    }
#undef AVF_LDGA
#undef AVF_STSA
#undef AVF_LDV

    const int lrow = lane >> 2;
    const int lcol = (lane & 3) * 2;
#pragma unroll
    for (int mt = 0; mt < 4; mt++) {
#pragma unroll
        for (int nt = 0; nt < 2; nt++) {
            const int row = bm + wm * 64 + mt * 16 + lrow;
            const int col = wn * 16 + nt * 8 + lcol;
            const size_t o0 = (size_t)z * LSEQ * DK + (size_t)row * DK + col;
            const size_t o1 = (size_t)z * LSEQ * DK + (size_t)(row + 8) * DK + col;
            __nv_bfloat16 h0, h1, g0, g1;
            bf16_split2(d[mt][nt][0], h0, h1);
            bf16_split2(d[mt][nt][1], g0, g1);
            *(__nv_bfloat162*)&C0[o0] = __nv_bfloat162(h0, g0);
            *(__nv_bfloat162*)&C1[o0] = __nv_bfloat162(h1, g1);
            bf16_split2(d[mt][nt][2], h0, h1);
            bf16_split2(d[mt][nt][3], g0, g1);
            *(__nv_bfloat162*)&C0[o1] = __nv_bfloat162(h0, g0);
            *(__nv_bfloat162*)&C1[o1] = __nv_bfloat162(h1, g1);
        }
    }
}

// ---------------------------------------------------------------------------
extern "C" void kernel_launch(void* const* d_in, const int* in_sizes, int n_in,
                              void* d_out, int out_size)
{
    const float* x  = (const float*)d_in[0];
    const float* y  = (const float*)d_in[1];
    const float* Wq = (const float*)d_in[2];
    const float* bq = (const float*)d_in[3];
    const float* Wk = (const float*)d_in[4];
    const float* bk = (const float*)d_in[5];
    const float* Wv = (const float*)d_in[6];
    const float* bv = (const float*)d_in[7];
    const float* Wo = (const float*)d_in[8];
    const float* bo = (const float*)d_in[9];
    float* out = (float*)d_out;

    float *gQ, *gK, *gV, *gS;
    cudaGetSymbolAddress((void**)&gQ, g_Q);
    cudaGetSymbolAddress((void**)&gK, g_K);
    cudaGetSymbolAddress((void**)&gV, g_V);
    cudaGetSymbolAddress((void**)&gS, g_S);
    __nv_bfloat16 *y0, *y1, *c0, *c1, *v0t, *v1t;
    __nv_bfloat16 *wv0, *wv1, *wo0, *wo1;
    cudaGetSymbolAddress((void**)&y0, g_y0);
    cudaGetSymbolAddress((void**)&y1, g_y1);
    cudaGetSymbolAddress((void**)&c0, g_c0);
    cudaGetSymbolAddress((void**)&c1, g_c1);
    cudaGetSymbolAddress((void**)&v0t, g_v0t);
    cudaGetSymbolAddress((void**)&v1t, g_v1t);
    cudaGetSymbolAddress((void**)&wv0, g_wv0);
    cudaGetSymbolAddress((void**)&wv1, g_wv1);
    cudaGetSymbolAddress((void**)&wo0, g_wo0);
    cudaGetSymbolAddress((void**)&wo1, g_wo1);

    cudaFuncSetAttribute(gemm_bf16x3, cudaFuncAttributeMaxDynamicSharedMemorySize,
                         GEMM3_SMEM_BYTES);
    cudaFuncSetAttribute(av_fused, cudaFuncAttributeMaxDynamicSharedMemorySize,
                         AVF_SMEM);

    cudaEvent_t eFork, eK, eB;
    cudaEventCreateWithFlags(&eFork, cudaEventDisableTiming);
    cudaEventCreateWithFlags(&eK, cudaEventDisableTiming);
    cudaEventCreateWithFlags(&eB, cudaEventDisableTiming);

    const cudaStream_t sMain = 0;
    const cudaStream_t sSide = cudaStreamPerThread;

    dim3 tt(32, 8);
    dim3 tg(32, 32);
    dim3 gGemm(D_MODEL / 128, NTOK / 128);  // (8, 64)
    dim3 gScore(LSEQ / 128, LSEQ / 128, NPAIR);
    dim3 gVtG(DK / 32, LSEQ / 32, NPAIR);
    dim3 gAV(LSEQ / 128, NPAIR);
    const int n4 = NTOK * D_MODEL / 4;

    cudaEventRecord(eFork, sMain);
    cudaStreamWaitEvent(sSide, eFork, 0);

    // Side lane: K projection (bit-exact), then the tensor-prep chain.
    sgemm_bias_kernel<<<gGemm, 256, 0, sSide>>>(y, Wk, bk, gK, NTOK, D_MODEL, D_MODEL);
    cudaEventRecord(eK, sSide);
    split2_kernel<<<(n4 + 255) / 256, 256, 0, sSide>>>(y, y0, y1, n4);
    split2_transpose_kernel<<<tg, tt, 0, sSide>>>(Wv, wv0, wv1);
    split2_transpose_kernel<<<tg, tt, 0, sSide>>>(Wo, wo0, wo1);
    gemm_bf16x3<<<gGemm, 256, GEMM3_SMEM_BYTES, sSide>>>(y0, y1, wv0, wv1, bv, gV,
                                                         NTOK, D_MODEL, D_MODEL);
    vt_split_kernel<<<gVtG, tt, 0, sSide>>>(gV, v0t, v1t);
    cudaEventRecord(eB, sSide);

    // Main lane: Q projection concurrent with side lane.
    sgemm_bias_kernel<<<gGemm, 256, 0, sMain>>>(x, Wq, bq, gQ, NTOK, D_MODEL, D_MODEL);

    cudaStreamWaitEvent(sMain, eK, 0);
    score_kernel<<<gScore, 256, 0, sMain>>>(gQ, gK, gS);

    cudaStreamWaitEvent(sMain, eB, 0);
    av_fused<<<gAV, 256, AVF_SMEM, sMain>>>(gS, v0t, v1t, c0, c1);

    gemm_bf16x3<<<gGemm, 256, GEMM3_SMEM_BYTES, sMain>>>(c0, c1, wo0, wo1, bo, out,
                                                         NTOK, D_MODEL, D_MODEL);
}

// round 11
// speedup vs baseline: 1.0209x; 1.0032x over previous
#include <cuda_runtime.h>
#include <cuda_bf16.h>
#include <cstdint>

// Problem constants
#define D_MODEL 1024
#define NTOK    8192          // B*L = 8*1024
#define NPAIR   128           // N_HEADS * B = 16*8
#define LSEQ    1024
#define DK      64

// ---------------------------------------------------------------------------
// Scratch (device globals — allocation-free rule)
// ---------------------------------------------------------------------------
__device__ float g_Q[NTOK * D_MODEL];
__device__ float g_K[NTOK * D_MODEL];
__device__ float g_V[NTOK * D_MODEL];
__device__ float g_S[(size_t)NPAIR * LSEQ * LSEQ];   // 512 MB scores

// bf16 split pairs
__device__ __nv_bfloat16 g_y0[NTOK * D_MODEL];
__device__ __nv_bfloat16 g_y1[NTOK * D_MODEL];
__device__ __nv_bfloat16 g_c0[NTOK * D_MODEL];       // AV out (split)
__device__ __nv_bfloat16 g_c1[NTOK * D_MODEL];
__device__ __nv_bfloat16 g_v0t[NTOK * D_MODEL];      // per-pair V^T split [64][1024]
__device__ __nv_bfloat16 g_v1t[NTOK * D_MODEL];
__device__ __nv_bfloat16 g_wv0[D_MODEL * D_MODEL];   // W^T splits
__device__ __nv_bfloat16 g_wv1[D_MODEL * D_MODEL];
__device__ __nv_bfloat16 g_wo0[D_MODEL * D_MODEL];
__device__ __nv_bfloat16 g_wo1[D_MODEL * D_MODEL];

// ---------------------------------------------------------------------------
// PTX helpers
// ---------------------------------------------------------------------------
__device__ __forceinline__ uint32_t smem_to_u32(const void* p) {
    uint32_t a;
    asm("{ .reg .u64 t; cvta.to.shared.u64 t, %1; cvt.u32.u64 %0, t; }" : "=r"(a) : "l"(p));
    return a;
}
__device__ __forceinline__ void cp_async16(uint32_t dst, const void* src) {
    asm volatile("cp.async.cg.shared.global [%0], [%1], 16;" :: "r"(dst), "l"(src));
}
#define CP_COMMIT() asm volatile("cp.async.commit_group;" ::: "memory")
#define CP_WAIT(n)  asm volatile("cp.async.wait_group %0;" :: "n"(n) : "memory")

__device__ __forceinline__ void ldmatrix_x4(uint32_t* r, uint32_t addr) {
    asm volatile("ldmatrix.sync.aligned.m8n8.x4.shared.b16 {%0,%1,%2,%3}, [%4];"
                 : "=r"(r[0]), "=r"(r[1]), "=r"(r[2]), "=r"(r[3]) : "r"(addr));
}
__device__ __forceinline__ void mma_bf16(float* d, const uint32_t* a, const uint32_t* b) {
    asm volatile(
        "mma.sync.aligned.m16n8k16.row.col.f32.bf16.bf16.f32 "
        "{%0,%1,%2,%3}, {%4,%5,%6,%7}, {%8,%9}, {%0,%1,%2,%3};"
        : "+f"(d[0]), "+f"(d[1]), "+f"(d[2]), "+f"(d[3])
        : "r"(a[0]), "r"(a[1]), "r"(a[2]), "r"(a[3]), "r"(b[0]), "r"(b[1]));
}

// Packed f32x2 FMA (sm_100+ base ISA): two independent IEEE fma.rn.f32.
__device__ __forceinline__ unsigned long long pack2(float x, float y) {
    unsigned long long r;
    asm("mov.b64 %0, {%1, %2};" : "=l"(r) : "f"(x), "f"(y));
    return r;
}
__device__ __forceinline__ void unpack2(unsigned long long r, float& x, float& y) {
    asm("mov.b64 {%0, %1}, %2;" : "=f"(x), "=f"(y) : "l"(r));
}
__device__ __forceinline__ void fma2p(unsigned long long& d, unsigned long long a,
                                      unsigned long long b) {
    asm("fma.rn.f32x2 %0, %1, %2, %3;" : "=l"(d) : "l"(a), "l"(b), "l"(d));
}

// 2-way bf16 split
__device__ __forceinline__ void bf16_split2(float f, __nv_bfloat16& h0, __nv_bfloat16& h1) {
    h0 = __float2bfloat16(f);
    h1 = __float2bfloat16(f - __bfloat162float(h0));
}

// ---------------------------------------------------------------------------
// [BIT-EXACT, FROZEN] Q/K projection: C[M,N] = A@B + bias, packed f32x2 FMAs.
// ---------------------------------------------------------------------------
__global__ __launch_bounds__(256) void sgemm_bias_kernel(
    const float* __restrict__ A, const float* __restrict__ B,
    const float* __restrict__ bias, float* __restrict__ C,
    int M, int N, int K)
{
    __shared__ float As[8][128];
    __shared__ float Bs[8][128];

    const int tid = threadIdx.x;
    const int bm = blockIdx.y * 128;
    const int bn = blockIdx.x * 128;

    const int trow = (tid / 16) * 8;
    const int tcol = (tid % 16) * 8;

    const int arow = tid / 2;
    const int acol = (tid % 2) * 4;
    const int brow = tid / 32;
    const int bcol = (tid % 32) * 4;

    unsigned long long acc2[8][4];
#pragma unroll
    for (int i = 0; i < 8; i++)
#pragma unroll
        for (int j = 0; j < 4; j++) acc2[i][j] = 0ull;

    for (int k0 = 0; k0 < K; k0 += 8) {
        float4 av = *(const float4*)&A[(size_t)(bm + arow) * K + k0 + acol];
        As[acol + 0][arow] = av.x;
        As[acol + 1][arow] = av.y;
        As[acol + 2][arow] = av.z;
        As[acol + 3][arow] = av.w;
        float4 bv = *(const float4*)&B[(size_t)(k0 + brow) * N + bn + bcol];
        *(float4*)&Bs[brow][bcol] = bv;
        __syncthreads();

#pragma unroll
        for (int k = 0; k < 8; k++) {
            float a[8], b[8];
            *(float4*)&a[0] = *(const float4*)&As[k][trow];
            *(float4*)&a[4] = *(const float4*)&As[k][trow + 4];
            *(float4*)&b[0] = *(const float4*)&Bs[k][tcol];
            *(float4*)&b[4] = *(const float4*)&Bs[k][tcol + 4];
            unsigned long long b2[4];
#pragma unroll
            for (int j = 0; j < 4; j++) b2[j] = pack2(b[2 * j], b[2 * j + 1]);
#pragma unroll
            for (int i = 0; i < 8; i++) {
                const unsigned long long a2 = pack2(a[i], a[i]);
#pragma unroll
                for (int j = 0; j < 4; j++) fma2p(acc2[i][j], a2, b2[j]);
            }
        }
        __syncthreads();
    }

    float bb[8];
    *(float4*)&bb[0] = *(const float4*)&bias[bn + tcol];
    *(float4*)&bb[4] = *(const float4*)&bias[bn + tcol + 4];

#pragma unroll
    for (int i = 0; i < 8; i++) {
        float acc[8];
#pragma unroll
        for (int j = 0; j < 4; j++) unpack2(acc2[i][j], acc[2 * j], acc[2 * j + 1]);
        const size_t r = (size_t)(bm + trow + i) * N + bn + tcol;
        float4 o0 = make_float4(acc[0] + bb[0], acc[1] + bb[1],
                                acc[2] + bb[2], acc[3] + bb[3]);
        float4 o1 = make_float4(acc[4] + bb[4], acc[5] + bb[5],
                                acc[6] + bb[6], acc[7] + bb[7]);
        *(float4*)&C[r] = o0;
        *(float4*)&C[r + 4] = o1;
    }
}

// ---------------------------------------------------------------------------
// [BIT-EXACT, FROZEN] Batched score: S[z] = Q[z]@K[z]^T * (1/32). Writes S.
// ---------------------------------------------------------------------------
__global__ __launch_bounds__(256) void score_kernel(
    const float* __restrict__ Q, const float* __restrict__ Km,
    float* __restrict__ S)
{
    __shared__ float As[8][128];
    __shared__ float Bs[8][128];

    const int z = blockIdx.z;
    const float* Qz = Q + (size_t)z * LSEQ * DK;
    const float* Kz = Km + (size_t)z * LSEQ * DK;
    float* Sz = S + (size_t)z * LSEQ * LSEQ;

    const int tid = threadIdx.x;
    const int bm = blockIdx.y * 128;
    const int bn = blockIdx.x * 128;
    const int trow = (tid / 16) * 8;
    const int tcol = (tid % 16) * 8;
    const int lrow = tid / 2;
    const int lcol = (tid % 2) * 4;

    unsigned long long acc2[8][4];
#pragma unroll
    for (int i = 0; i < 8; i++)
#pragma unroll
        for (int j = 0; j < 4; j++) acc2[i][j] = 0ull;

    for (int k0 = 0; k0 < DK; k0 += 8) {
        float4 av = *(const float4*)&Qz[(size_t)(bm + lrow) * DK + k0 + lcol];
        As[lcol + 0][lrow] = av.x;
        As[lcol + 1][lrow] = av.y;
        As[lcol + 2][lrow] = av.z;
        As[lcol + 3][lrow] = av.w;
        float4 bv = *(const float4*)&Kz[(size_t)(bn + lrow) * DK + k0 + lcol];
        Bs[lcol + 0][lrow] = bv.x;
        Bs[lcol + 1][lrow] = bv.y;
        Bs[lcol + 2][lrow] = bv.z;
        Bs[lcol + 3][lrow] = bv.w;
        __syncthreads();

#pragma unroll
        for (int k = 0; k < 8; k++) {
            float a[8], b[8];
            *(float4*)&a[0] = *(const float4*)&As[k][trow];
            *(float4*)&a[4] = *(const float4*)&As[k][trow + 4];
            *(float4*)&b[0] = *(const float4*)&Bs[k][tcol];
            *(float4*)&b[4] = *(const float4*)&Bs[k][tcol + 4];
            unsigned long long b2[4];
#pragma unroll
            for (int j = 0; j < 4; j++) b2[j] = pack2(b[2 * j], b[2 * j + 1]);
#pragma unroll
            for (int i = 0; i < 8; i++) {
                const unsigned long long a2 = pack2(a[i], a[i]);
#pragma unroll
                for (int j = 0; j < 4; j++) fma2p(acc2[i][j], a2, b2[j]);
            }
        }
        __syncthreads();
    }

    const float scale = 0.03125f;
#pragma unroll
    for (int i = 0; i < 8; i++) {
        float acc[8];
#pragma unroll
        for (int j = 0; j < 4; j++) unpack2(acc2[i][j], acc[2 * j], acc[2 * j + 1]);
        const size_t r = (size_t)(bm + trow + i) * LSEQ + bn + tcol;
        float4 o0 = make_float4(acc[0] * scale, acc[1] * scale,
                                acc[2] * scale, acc[3] * scale);
        float4 o1 = make_float4(acc[4] * scale, acc[5] * scale,
                                acc[6] * scale, acc[7] * scale);
        *(float4*)&Sz[r] = o0;
        *(float4*)&Sz[r + 4] = o1;
    }
}

// ---------------------------------------------------------------------------
// fp32 -> bf16 (hi, lo) split. n4 = elems/4.
// ---------------------------------------------------------------------------
__global__ __launch_bounds__(256) void split2_kernel(
    const float* __restrict__ in, __nv_bfloat16* __restrict__ o0,
    __nv_bfloat16* __restrict__ o1, int n4)
{
    int i = blockIdx.x * blockDim.x + threadIdx.x;
    if (i >= n4) return;
    float4 v = ((const float4*)in)[i];
    __nv_bfloat16 a0, a1, b0, b1, c0, c1, d0, d1;
    bf16_split2(v.x, a0, a1);
    bf16_split2(v.y, b0, b1);
    bf16_split2(v.z, c0, c1);
    bf16_split2(v.w, d0, d1);
    ((__nv_bfloat162*)o0)[i * 2 + 0] = __nv_bfloat162(a0, b0);
    ((__nv_bfloat162*)o0)[i * 2 + 1] = __nv_bfloat162(c0, d0);
    ((__nv_bfloat162*)o1)[i * 2 + 0] = __nv_bfloat162(a1, b1);
    ((__nv_bfloat162*)o1)[i * 2 + 1] = __nv_bfloat162(c1, d1);
}

// ---------------------------------------------------------------------------
// W [K][N] fp32 -> split bf16 transposed [N][K]
// ---------------------------------------------------------------------------
__global__ __launch_bounds__(256) void split2_transpose_kernel(
    const float* __restrict__ W, __nv_bfloat16* __restrict__ T0,
    __nv_bfloat16* __restrict__ T1)
{
    __shared__ float t[32][33];
    const int x0 = blockIdx.x * 32;
    const int y0 = blockIdx.y * 32;
    const int tx = threadIdx.x;
#pragma unroll
    for (int i = threadIdx.y; i < 32; i += 8)
        t[i][tx] = W[(size_t)(y0 + i) * D_MODEL + x0 + tx];
    __syncthreads();
#pragma unroll
    for (int i = threadIdx.y; i < 32; i += 8) {
        float v = t[tx][i];
        __nv_bfloat16 h0, h1;
        bf16_split2(v, h0, h1);
        size_t o = (size_t)(x0 + i) * D_MODEL + y0 + tx;
        T0[o] = h0;
        T1[o] = h1;
    }
}

// ---------------------------------------------------------------------------
// Batched V^T + split: v{0,1}t[z][d][l] = split(V[z][l][d]).
// ---------------------------------------------------------------------------
__global__ __launch_bounds__(256) void vt_split_kernel(
    const float* __restrict__ V, __nv_bfloat16* __restrict__ T0,
    __nv_bfloat16* __restrict__ T1)
{
    __shared__ float t[32][33];
    const int z = blockIdx.z;
    const float* Vz = V + (size_t)z * LSEQ * DK;
    const int x0 = blockIdx.x * 32;  // d base
    const int y0 = blockIdx.y * 32;  // l base
    const int tx = threadIdx.x;
#pragma unroll
    for (int i = threadIdx.y; i < 32; i += 8)
        t[i][tx] = Vz[(size_t)(y0 + i) * DK + x0 + tx];
    __syncthreads();
#pragma unroll
    for (int i = threadIdx.y; i < 32; i += 8) {
        float v = t[tx][i];
        __nv_bfloat16 h0, h1;
        bf16_split2(v, h0, h1);
        size_t o = (size_t)z * LSEQ * DK + (size_t)(x0 + i) * LSEQ + y0 + tx;
        T0[o] = h0;
        T1[o] = h1;
    }
}

// ---------------------------------------------------------------------------
// bf16x3 GEMM: C = (A0+A1)@(B0+B1)^T + bias  (keeps a0b0, a0b1, a1b0)
// ---------------------------------------------------------------------------
#define ROWB 80
#define MATB (128 * ROWB)               // 10240
#define STAGE3B (4 * MATB)              // 40960 (a0,a1,b0,b1)
#define GEMM3_SMEM_BYTES (2 * STAGE3B)  // 81920

__global__ __launch_bounds__(256) void gemm_bf16x3(
    const __nv_bfloat16* __restrict__ A0, const __nv_bfloat16* __restrict__ A1,
    const __nv_bfloat16* __restrict__ B0, const __nv_bfloat16* __restrict__ B1,
    const float* __restrict__ bias, float* __restrict__ C, int M, int N, int K)
{
    extern __shared__ char smem[];
    const uint32_t sb = smem_to_u32(smem);
    const int tid = threadIdx.x;
    const int lane = tid & 31;
    const int wid = tid >> 5;
    const int wm = wid >> 2;
    const int wn = wid & 3;
    const int bm = blockIdx.y * 128;
    const int bn = blockIdx.x * 128;
    const int nkc = K / 32;

    float d[4][4][4];
#pragma unroll
    for (int i = 0; i < 4; i++)
#pragma unroll
        for (int j = 0; j < 4; j++)
#pragma unroll
            for (int k = 0; k < 4; k++) d[i][j][k] = 0.f;

#define G3_LOAD(stb, k0)                                                      \
    do {                                                                      \
        _Pragma("unroll")                                                     \
        for (int t = 0; t < 2; t++) {                                         \
            const int idx = tid + t * 256;                                    \
            const int row = idx >> 2, ch = idx & 3;                           \
            const uint32_t off = (uint32_t)(row * ROWB + ch * 16);            \
            const size_t ga = (size_t)(bm + row) * K + (k0) + ch * 8;         \
            const size_t gb = (size_t)(bn + row) * K + (k0) + ch * 8;         \
            cp_async16((stb) + 0 * MATB + off, A0 + ga);                      \
            cp_async16((stb) + 1 * MATB + off, A1 + ga);                      \
            cp_async16((stb) + 2 * MATB + off, B0 + gb);                      \
            cp_async16((stb) + 3 * MATB + off, B1 + gb);                      \
        }                                                                     \
    } while (0)

    G3_LOAD(sb, 0);
    CP_COMMIT();
    G3_LOAD(sb + STAGE3B, 32);
    CP_COMMIT();

    const int a_rowsel = lane & 15;
    const uint32_t a_koff = (uint32_t)((lane >> 4) << 4);
    const int b_nsel = (lane & 7) + ((lane >> 4) << 3);
    const uint32_t b_koff = (uint32_t)(((lane >> 3) & 1) << 4);

    for (int kc = 0; kc < nkc; kc++) {
        if (kc + 1 < nkc) { CP_WAIT(1); } else { CP_WAIT(0); }
        __syncthreads();

        const uint32_t st = sb + (kc & 1) * STAGE3B;

#pragma unroll
        for (int ks = 0; ks < 2; ks++) {
            const uint32_t kb = ks * 32;

            uint32_t a0[4][4], a1[4][4];
            uint32_t b0[4][2], b1[4][2];
#pragma unroll
            for (int mt = 0; mt < 4; mt++) {
                const uint32_t ra = (uint32_t)((wm * 64 + mt * 16 + a_rowsel) * ROWB) + kb + a_koff;
                ldmatrix_x4(a0[mt], st + 0 * MATB + ra);
                ldmatrix_x4(a1[mt], st + 1 * MATB + ra);
            }
#pragma unroll
            for (int ntp = 0; ntp < 2; ntp++) {
                const uint32_t rb = (uint32_t)((wn * 32 + ntp * 16 + b_nsel) * ROWB) + kb + b_koff;
                uint32_t t0[4], t1[4];
                ldmatrix_x4(t0, st + 2 * MATB + rb);
                ldmatrix_x4(t1, st + 3 * MATB + rb);
                b0[ntp * 2 + 0][0] = t0[0]; b0[ntp * 2 + 0][1] = t0[1];
                b0[ntp * 2 + 1][0] = t0[2]; b0[ntp * 2 + 1][1] = t0[3];
                b1[ntp * 2 + 0][0] = t1[0]; b1[ntp * 2 + 0][1] = t1[1];
                b1[ntp * 2 + 1][0] = t1[2]; b1[ntp * 2 + 1][1] = t1[3];
            }

#pragma unroll
            for (int mt = 0; mt < 4; mt++)
#pragma unroll
                for (int nt = 0; nt < 4; nt++) {
                    mma_bf16(d[mt][nt], a0[mt], b1[nt]);
                    mma_bf16(d[mt][nt], a1[mt], b0[nt]);
                    mma_bf16(d[mt][nt], a0[mt], b0[nt]);
                }
        }

        __syncthreads();
        if (kc + 2 < nkc) {
            const uint32_t st2 = sb + (kc & 1) * STAGE3B;
            G3_LOAD(st2, (kc + 2) * 32);
        }
        CP_COMMIT();
    }
#undef G3_LOAD

    const int lrow = lane >> 2;
    const int lcol = (lane & 3) * 2;
#pragma unroll
    for (int mt = 0; mt < 4; mt++) {
#pragma unroll
        for (int nt = 0; nt < 4; nt++) {
            const int row = bm + wm * 64 + mt * 16 + lrow;
            const int col = bn + wn * 32 + nt * 8 + lcol;
            const float bb0 = bias[col], bb1 = bias[col + 1];
            float2 v0 = make_float2(d[mt][nt][0] + bb0, d[mt][nt][1] + bb1);
            float2 v1 = make_float2(d[mt][nt][2] + bb0, d[mt][nt][3] + bb1);
            *(float2*)&C[(size_t)row * N + col] = v0;
            *(float2*)&C[(size_t)(row + 8) * N + col] = v1;
        }
    }
}

// ---------------------------------------------------------------------------
// Fused stats + softmax + AV:  O[z] = softmax(mask(S[z])) @ Vt[z]^T.
// Phase 1: exact R1-tree row stats (verbatim from R10-validated kernel).
// Phase 2: AV mainloop; S tiles staged via cp.async (fp32, 144B rows), then
//          LDS -> mask/__expf/*inv (identical ops/bits) -> STS bf16 P tiles.
// grid (LSEQ/128, NPAIR), 256 threads.
// ---------------------------------------------------------------------------
#define SBUF_ROWB 144                        // 36 floats per row (conflict pad)
#define AVF_SB (128 * SBUF_ROWB)             // 18432 per S stage
#define AVF_AB (128 * ROWB)                  // 10240 per P-split tile
#define AVF_BB (64 * ROWB)                   // 5120 per V-split tile
#define AVF_S_OFF 0                          // 2 x 18432 = 36864
#define AVF_P_OFF (2 * AVF_SB)               // 36864: 2 stages x (P0,P1)
#define AVF_PST (2 * AVF_AB)                 // 20480 per stage
#define AVF_V_OFF (AVF_P_OFF + 2 * AVF_PST)  // 77824: 2 stages x (V0,V1)
#define AVF_VST (2 * AVF_BB)                 // 10240 per stage
#define AVF_STATM (AVF_V_OFF + 2 * AVF_VST)  // 98304
#define AVF_STATX (AVF_STATM + 512)
#define AVF_STATI (AVF_STATX + 512)
#define AVF_RED   (AVF_STATI + 512)          // 3 x [16][2] floats = 384B
#define AVF_SMEM  (AVF_RED + 384)            // 100224

__global__ __launch_bounds__(256) void av_fused(
    const float* __restrict__ S,
    const __nv_bfloat16* __restrict__ V0, const __nv_bfloat16* __restrict__ V1,
    __nv_bfloat16* __restrict__ C0, __nv_bfloat16* __restrict__ C1)
{
    extern __shared__ char smem[];
    const uint32_t sb = smem_to_u32(smem);
    const int tid = threadIdx.x;
    const int lane = tid & 31;
    const int wid = tid >> 5;
    const int wm = wid >> 2;
    const int wn = wid & 3;
    const int z = blockIdx.y;
    const int bm = blockIdx.x * 128;
    const float* Sz = S + ((size_t)z * LSEQ + bm) * LSEQ;   // local rows 0..127
    const __nv_bfloat16* V0z = V0 + (size_t)z * LSEQ * DK;
    const __nv_bfloat16* V1z = V1 + (size_t)z * LSEQ * DK;

    float* statM = (float*)(smem + AVF_STATM);
    float* statX = (float*)(smem + AVF_STATX);
    float* statI = (float*)(smem + AVF_STATI);
    float (*rbM)[2] = (float(*)[2])(smem + AVF_RED);
    float (*rbX)[2] = rbM + 16;
    float (*rbE)[2] = rbM + 32;

    // ================= Phase 1: exact-tree row stats (R10-validated) =======
    {
        const int rowgrp = tid >> 6;     // 0..3
        const int u = tid & 63;          // 0..63
        const int u5 = u >> 5;
        const int rl = rowgrp * 4;

        for (int it = 0; it < 8; it++) {
            float s[4][16];
#pragma unroll
            for (int r = 0; r < 4; r++)
#pragma unroll
                for (int e = 0; e < 4; e++)
                    *(float4*)&s[r][4 * e] =
                        *(const float4*)&Sz[(size_t)(it * 16 + rl + r) * LSEQ + 4 * u + 256 * e];

            float mean[4], rowmax[4], inv[4];

            // ---- mean (exact R1 tree) ----
#pragma unroll
            for (int r = 0; r < 4; r++) {
                float pe[4];
#pragma unroll
                for (int e = 0; e < 4; e++)
                    pe[e] = ((s[r][4 * e] + s[r][4 * e + 1]) + s[r][4 * e + 2]) + s[r][4 * e + 3];
#pragma unroll
                for (int o = 16; o > 0; o >>= 1)
#pragma unroll
                    for (int e = 0; e < 4; e++)
                        pe[e] += __shfl_xor_sync(0xffffffffu, pe[e], o);
                const float half = (pe[0] + pe[2]) + (pe[1] + pe[3]);
                if ((tid & 31) == 0) rbM[rl + r][u5] = half;
            }
            __syncthreads();
#pragma unroll
            for (int r = 0; r < 4; r++)
                mean[r] = (rbM[rl + r][0] + rbM[rl + r][1]) * (1.0f / 1024.0f);

            // ---- masked max (order-free) ----
#pragma unroll
            for (int r = 0; r < 4; r++) {
                float m = -3.402823466e38f;
#pragma unroll
                for (int c = 0; c < 16; c++)
                    if (s[r][c] > mean[r]) m = fmaxf(m, s[r][c]);
#pragma unroll
                for (int o = 16; o > 0; o >>= 1)
                    m = fmaxf(m, __shfl_xor_sync(0xffffffffu, m, o));
                if ((tid & 31) == 0) rbX[rl + r][u5] = m;
            }
            __syncthreads();
#pragma unroll
            for (int r = 0; r < 4; r++)
                rowmax[r] = fmaxf(rbX[rl + r][0], rbX[rl + r][1]);

            // ---- exp + sum (exact R1 tree) ----
#pragma unroll
            for (int r = 0; r < 4; r++) {
#pragma unroll
                for (int c = 0; c < 16; c++)
                    s[r][c] = (s[r][c] > mean[r]) ? __expf(s[r][c] - rowmax[r]) : 0.f;
                float pe[4];
#pragma unroll
                for (int e = 0; e < 4; e++)
                    pe[e] = ((s[r][4 * e] + s[r][4 * e + 1]) + s[r][4 * e + 2]) + s[r][4 * e + 3];
#pragma unroll
                for (int o = 16; o > 0; o >>= 1)
#pragma unroll
                    for (int e = 0; e < 4; e++)
                        pe[e] += __shfl_xor_sync(0xffffffffu, pe[e], o);
                const float half = (pe[0] + pe[2]) + (pe[1] + pe[3]);
                if ((tid & 31) == 0) rbE[rl + r][u5] = half;
            }
            __syncthreads();
#pragma unroll
            for (int r = 0; r < 4; r++)
                inv[r] = 1.0f / (rbE[rl + r][0] + rbE[rl + r][1]);

            if (u == 0) {
#pragma unroll
                for (int r = 0; r < 4; r++) {
                    statM[it * 16 + rl + r] = mean[r];
                    statX[it * 16 + rl + r] = rowmax[r];
                    statI[it * 16 + rl + r] = inv[r];
                }
            }
            __syncthreads();
        }
    }

    // ================= Phase 2: cp.async-staged AV with inline softmax ======
    float d[4][2][4];
#pragma unroll
    for (int i = 0; i < 4; i++)
#pragma unroll
        for (int j = 0; j < 2; j++)
#pragma unroll
            for (int k = 0; k < 4; k++) d[i][j][k] = 0.f;

    // Issue S (128x32 fp32) + V (64x32 bf16 pair) tiles for stage kc.
#define AVF_ISSUE(kc)                                                         \
    do {                                                                      \
        const uint32_t sbuf = sb + AVF_S_OFF + ((kc) & 1) * AVF_SB;           \
        _Pragma("unroll")                                                     \
        for (int t = 0; t < 4; t++) {                                         \
            const int idx = tid + t * 256;                                    \
            const int row = idx >> 3, ch = idx & 7;                           \
            cp_async16(sbuf + (uint32_t)(row * SBUF_ROWB + ch * 16),          \
                       Sz + (size_t)row * LSEQ + (kc) * 32 + ch * 4);         \
        }                                                                     \
        const uint32_t vb = sb + AVF_V_OFF + ((kc) & 1) * AVF_VST;            \
        const int vrow = tid >> 2, chv = tid & 3;                             \
        if (vrow < 64) {                                                      \
            const uint32_t off = (uint32_t)(vrow * ROWB + chv * 16);          \
            const size_t gb = (size_t)vrow * LSEQ + (kc) * 32 + chv * 8;      \
            cp_async16(vb + off, V0z + gb);                                   \
            cp_async16(vb + AVF_BB + off, V1z + gb);                          \
        }                                                                     \
    } while (0)

    // Convert S tile (smem fp32) -> P tile (smem bf16 pair), inline softmax.
#define AVF_CONVERT(kc)                                                       \
    do {                                                                      \
        const char* sbuf = smem + AVF_S_OFF + ((kc) & 1) * AVF_SB;            \
        char* pb = smem + AVF_P_OFF + ((kc) & 1) * AVF_PST;                   \
        _Pragma("unroll")                                                     \
        for (int t = 0; t < 4; t++) {                                         \
            const int idx = tid + t * 256;                                    \
            const int row = idx >> 3, ch = idx & 7;                           \
            float4 sv = *(const float4*)(sbuf + row * SBUF_ROWB + ch * 16);   \
            const float mu = statM[row], mx = statX[row], iv = statI[row];    \
            float svv[4] = {sv.x, sv.y, sv.z, sv.w};                          \
            __nv_bfloat16 h0[4], h1[4];                                       \
            _Pragma("unroll")                                                 \
            for (int j = 0; j < 4; j++) {                                     \
                float e = (svv[j] > mu) ? __expf(svv[j] - mx) : 0.f;          \
                float p = e * iv;                                             \
                bf16_split2(p, h0[j], h1[j]);                                 \
            }                                                                 \
            __nv_bfloat162* p0p = (__nv_bfloat162*)(pb + row * ROWB + ch * 8);\
            __nv_bfloat162* p1p = (__nv_bfloat162*)(pb + AVF_AB + row * ROWB + ch * 8);\
            p0p[0] = __nv_bfloat162(h0[0], h0[1]);                            \
            p0p[1] = __nv_bfloat162(h0[2], h0[3]);                            \
            p1p[0] = __nv_bfloat162(h1[0], h1[1]);                            \
            p1p[1] = __nv_bfloat162(h1[2], h1[3]);                            \
        }                                                                     \
    } while (0)

    // Prologue: stages 0,1 in flight; convert P(0).
    AVF_ISSUE(0); CP_COMMIT();
    AVF_ISSUE(1); CP_COMMIT();
    CP_WAIT(1);
    __syncthreads();
    AVF_CONVERT(0);
    __syncthreads();

    const int a_rowsel = lane & 15;
    const uint32_t a_koff = (uint32_t)((lane >> 4) << 4);
    const int b_nsel = (lane & 7) + ((lane >> 4) << 3);
    const uint32_t b_koff = (uint32_t)(((lane >> 3) & 1) << 4);

    const int nkc = LSEQ / 32;   // 32
    for (int kc = 0; kc < nkc; kc++) {
        const uint32_t ast = sb + AVF_P_OFF + (kc & 1) * AVF_PST;
        const uint32_t vst = sb + AVF_V_OFF + (kc & 1) * AVF_VST;

#pragma unroll
        for (int ks = 0; ks < 2; ks++) {
            const uint32_t kb = ks * 32;

            uint32_t a0[4][4], a1[4][4];
#pragma unroll
            for (int mt = 0; mt < 4; mt++) {
                const uint32_t ra = (uint32_t)((wm * 64 + mt * 16 + a_rowsel) * ROWB) + kb + a_koff;
                ldmatrix_x4(a0[mt], ast + ra);
                ldmatrix_x4(a1[mt], ast + AVF_AB + ra);
            }
            uint32_t b0[2][2], b1[2][2];
            {
                const uint32_t rb = (uint32_t)((wn * 16 + b_nsel) * ROWB) + kb + b_koff;
                uint32_t t0[4], t1[4];
                ldmatrix_x4(t0, vst + rb);
                ldmatrix_x4(t1, vst + AVF_BB + rb);
                b0[0][0] = t0[0]; b0[0][1] = t0[1];
                b0[1][0] = t0[2]; b0[1][1] = t0[3];
                b1[0][0] = t1[0]; b1[0][1] = t1[1];
                b1[1][0] = t1[2]; b1[1][1] = t1[3];
            }

#pragma unroll
            for (int mt = 0; mt < 4; mt++)
#pragma unroll
                for (int nt = 0; nt < 2; nt++) {
                    mma_bf16(d[mt][nt], a0[mt], b1[nt]);
                    mma_bf16(d[mt][nt], a1[mt], b0[nt]);
                    mma_bf16(d[mt][nt], a0[mt], b0[nt]);
                }
        }

        __syncthreads();   // readers done with P(kc)/V(kc)/S-slot(kc)
        if (kc + 2 < nkc) { AVF_ISSUE(kc + 2); CP_COMMIT(); }
        if (kc + 1 < nkc) {
            if (kc + 2 < nkc) { CP_WAIT(1); } else { CP_WAIT(0); }
            __syncthreads();          // S(kc+1)/V(kc+1) visible
            AVF_CONVERT(kc + 1);
            __syncthreads();          // P(kc+1) visible for next mma
        }
    }
#undef AVF_ISSUE
#undef AVF_CONVERT

    const int lrow = lane >> 2;
    const int lcol = (lane & 3) * 2;
#pragma unroll
    for (int mt = 0; mt < 4; mt++) {
#pragma unroll
        for (int nt = 0; nt < 2; nt++) {
            const int row = bm + wm * 64 + mt * 16 + lrow;
            const int col = wn * 16 + nt * 8 + lcol;
            const size_t o0 = (size_t)z * LSEQ * DK + (size_t)row * DK + col;
            const size_t o1 = (size_t)z * LSEQ * DK + (size_t)(row + 8) * DK + col;
            __nv_bfloat16 h0, h1, g0, g1;
            bf16_split2(d[mt][nt][0], h0, h1);
            bf16_split2(d[mt][nt][1], g0, g1);
            *(__nv_bfloat162*)&C0[o0] = __nv_bfloat162(h0, g0);
            *(__nv_bfloat162*)&C1[o0] = __nv_bfloat162(h1, g1);
            bf16_split2(d[mt][nt][2], h0, h1);
            bf16_split2(d[mt][nt][3], g0, g1);
            *(__nv_bfloat162*)&C0[o1] = __nv_bfloat162(h0, g0);
            *(__nv_bfloat162*)&C1[o1] = __nv_bfloat162(h1, g1);
        }
    }
}

// ---------------------------------------------------------------------------
extern "C" void kernel_launch(void* const* d_in, const int* in_sizes, int n_in,
                              void* d_out, int out_size)
{
    const float* x  = (const float*)d_in[0];
    const float* y  = (const float*)d_in[1];
    const float* Wq = (const float*)d_in[2];
    const float* bq = (const float*)d_in[3];
    const float* Wk = (const float*)d_in[4];
    const float* bk = (const float*)d_in[5];
    const float* Wv = (const float*)d_in[6];
    const float* bv = (const float*)d_in[7];
    const float* Wo = (const float*)d_in[8];
    const float* bo = (const float*)d_in[9];
    float* out = (float*)d_out;

    float *gQ, *gK, *gV, *gS;
    cudaGetSymbolAddress((void**)&gQ, g_Q);
    cudaGetSymbolAddress((void**)&gK, g_K);
    cudaGetSymbolAddress((void**)&gV, g_V);
    cudaGetSymbolAddress((void**)&gS, g_S);
    __nv_bfloat16 *y0, *y1, *c0, *c1, *v0t, *v1t;
    __nv_bfloat16 *wv0, *wv1, *wo0, *wo1;
    cudaGetSymbolAddress((void**)&y0, g_y0);
    cudaGetSymbolAddress((void**)&y1, g_y1);
    cudaGetSymbolAddress((void**)&c0, g_c0);
    cudaGetSymbolAddress((void**)&c1, g_c1);
    cudaGetSymbolAddress((void**)&v0t, g_v0t);
    cudaGetSymbolAddress((void**)&v1t, g_v1t);
    cudaGetSymbolAddress((void**)&wv0, g_wv0);
    cudaGetSymbolAddress((void**)&wv1, g_wv1);
    cudaGetSymbolAddress((void**)&wo0, g_wo0);
    cudaGetSymbolAddress((void**)&wo1, g_wo1);

    cudaFuncSetAttribute(gemm_bf16x3, cudaFuncAttributeMaxDynamicSharedMemorySize,
                         GEMM3_SMEM_BYTES);
    cudaFuncSetAttribute(av_fused, cudaFuncAttributeMaxDynamicSharedMemorySize,
                         AVF_SMEM);

    cudaEvent_t eFork, eK, eB;
    cudaEventCreateWithFlags(&eFork, cudaEventDisableTiming);
    cudaEventCreateWithFlags(&eK, cudaEventDisableTiming);
    cudaEventCreateWithFlags(&eB, cudaEventDisableTiming);

    const cudaStream_t sMain = 0;
    const cudaStream_t sSide = cudaStreamPerThread;

    dim3 tt(32, 8);
    dim3 tg(32, 32);
    dim3 gGemm(D_MODEL / 128, NTOK / 128);  // (8, 64)
    dim3 gScore(LSEQ / 128, LSEQ / 128, NPAIR);
    dim3 gVtG(DK / 32, LSEQ / 32, NPAIR);
    dim3 gAV(LSEQ / 128, NPAIR);
    const int n4 = NTOK * D_MODEL / 4;

    cudaEventRecord(eFork, sMain);
    cudaStreamWaitEvent(sSide, eFork, 0);

    // Side lane: K projection (bit-exact), then the tensor-prep chain.
    sgemm_bias_kernel<<<gGemm, 256, 0, sSide>>>(y, Wk, bk, gK, NTOK, D_MODEL, D_MODEL);
    cudaEventRecord(eK, sSide);
    split2_kernel<<<(n4 + 255) / 256, 256, 0, sSide>>>(y, y0, y1, n4);
    split2_transpose_kernel<<<tg, tt, 0, sSide>>>(Wv, wv0, wv1);
    split2_transpose_kernel<<<tg, tt, 0, sSide>>>(Wo, wo0, wo1);
    gemm_bf16x3<<<gGemm, 256, GEMM3_SMEM_BYTES, sSide>>>(y0, y1, wv0, wv1, bv, gV,
                                                         NTOK, D_MODEL, D_MODEL);
    vt_split_kernel<<<gVtG, tt, 0, sSide>>>(gV, v0t, v1t);
    cudaEventRecord(eB, sSide);

    // Main lane: Q projection concurrent with side lane.
    sgemm_bias_kernel<<<gGemm, 256, 0, sMain>>>(x, Wq, bq, gQ, NTOK, D_MODEL, D_MODEL);

    cudaStreamWaitEvent(sMain, eK, 0);
    score_kernel<<<gScore, 256, 0, sMain>>>(gQ, gK, gS);

    cudaStreamWaitEvent(sMain, eB, 0);
    av_fused<<<gAV, 256, AVF_SMEM, sMain>>>(gS, v0t, v1t, c0, c1);

    gemm_bf16x3<<<gGemm, 256, GEMM3_SMEM_BYTES, sMain>>>(c0, c1, wo0, wo1, bo, out,
                                                         NTOK, D_MODEL, D_MODEL);
}